// round 1
// baseline (speedup 1.0000x reference)
#include <cuda_runtime.h>
#include <math.h>

// Problem constants (from reference)
#define S_LEN   2048
#define D_MODEL 2048
#define L_LAT   512
#define BATCH   2
#define NHEADS  16
#define HDIM    128
#define M_ROWS  (BATCH * S_LEN)   // 4096
#define WINDOW  128
#define PERSIST 16

// ---------------------------------------------------------------------------
// Scratch (static __device__ arrays: no allocation allowed)
// ---------------------------------------------------------------------------
__device__ float g_Q [(size_t)M_ROWS * D_MODEL];   // 33.5 MB
__device__ float g_KV[(size_t)M_ROWS * L_LAT];     //  8.4 MB
__device__ float g_K [(size_t)M_ROWS * D_MODEL];   // 33.5 MB
__device__ float g_V [(size_t)M_ROWS * D_MODEL];   // 33.5 MB
__device__ float g_AO[(size_t)M_ROWS * D_MODEL];   // 33.5 MB

// ---------------------------------------------------------------------------
// SGEMM: C[M,N] = A[M,K] @ B[K,N], all row-major fp32.
// 128x128 block tile, BK=8, 256 threads, 8x8 per thread, double-buffered smem.
// Requires M%128==0, N%128==0, K%8==0 (true for all launches here).
// ---------------------------------------------------------------------------
__global__ __launch_bounds__(256)
void sgemm128x128(const float* __restrict__ A, const float* __restrict__ B,
                  float* __restrict__ C, int M, int N, int K)
{
    __shared__ float As[2][8][132];   // transposed A tile, padded rows
    __shared__ float Bs[2][8][128];

    const int t  = threadIdx.x;
    const int bm = blockIdx.y * 128;
    const int bn = blockIdx.x * 128;
    const int ty = t >> 4;            // 0..15
    const int tx = t & 15;            // 0..15

    // global-load assignments
    const int a_r = t >> 1;           // 0..127
    const int a_c = (t & 1) * 4;      // 0 or 4
    const int b_r = t >> 5;           // 0..7
    const int b_c = (t & 31) * 4;     // 0..124

    const float* Ap = A + (size_t)(bm + a_r) * K + a_c;
    const float* Bp = B + (size_t)b_r * N + bn + b_c;

    // preload tile 0 into buffer 0
    {
        float4 af = *(const float4*)(Ap);
        float4 bf = *(const float4*)(Bp);
        As[0][a_c + 0][a_r] = af.x;
        As[0][a_c + 1][a_r] = af.y;
        As[0][a_c + 2][a_r] = af.z;
        As[0][a_c + 3][a_r] = af.w;
        *(float4*)(&Bs[0][b_r][b_c]) = bf;
    }
    __syncthreads();

    float acc[8][8];
#pragma unroll
    for (int j = 0; j < 8; j++)
#pragma unroll
        for (int i = 0; i < 8; i++) acc[j][i] = 0.0f;

    const int ntiles = K >> 3;
    int buf = 0;
    for (int tile = 0; tile < ntiles; tile++) {
        float4 afn, bfn;
        const bool more = (tile + 1) < ntiles;
        if (more) {
            afn = *(const float4*)(Ap + (tile + 1) * 8);
            bfn = *(const float4*)(Bp + (size_t)(tile + 1) * 8 * N);
        }
#pragma unroll
        for (int kk = 0; kk < 8; kk++) {
            float ar[8], br[8];
            *(float4*)(&ar[0]) = *(const float4*)(&As[buf][kk][ty * 8]);
            *(float4*)(&ar[4]) = *(const float4*)(&As[buf][kk][ty * 8 + 4]);
            *(float4*)(&br[0]) = *(const float4*)(&Bs[buf][kk][tx * 8]);
            *(float4*)(&br[4]) = *(const float4*)(&Bs[buf][kk][tx * 8 + 4]);
#pragma unroll
            for (int j = 0; j < 8; j++)
#pragma unroll
                for (int i = 0; i < 8; i++)
                    acc[j][i] += ar[j] * br[i];
        }
        if (more) {
            const int nb = buf ^ 1;
            As[nb][a_c + 0][a_r] = afn.x;
            As[nb][a_c + 1][a_r] = afn.y;
            As[nb][a_c + 2][a_r] = afn.z;
            As[nb][a_c + 3][a_r] = afn.w;
            *(float4*)(&Bs[nb][b_r][b_c]) = bfn;
            __syncthreads();
            buf = nb;
        }
    }

#pragma unroll
    for (int j = 0; j < 8; j++) {
        float* Cp = C + (size_t)(bm + ty * 8 + j) * N + bn + tx * 8;
        *(float4*)(Cp)     = make_float4(acc[j][0], acc[j][1], acc[j][2], acc[j][3]);
        *(float4*)(Cp + 4) = make_float4(acc[j][4], acc[j][5], acc[j][6], acc[j][7]);
    }
}

// ---------------------------------------------------------------------------
// Windowed causal attention with persistent sink, flash-style online softmax.
// One block = one (batch, head, 64-query tile). 256 threads.
// Key chunks of 64; chunks fully outside (window union sink union causal) are skipped.
// ---------------------------------------------------------------------------
#define AT_SQ   64
#define AT_CK   64
#define AT_PAD  129    // row stride for Qs / KVs (conflict-free for strided row access)
#define AT_PPAD 65     // row stride for P
#define AT_SMEM_FLOATS (AT_SQ * AT_PAD + AT_CK * AT_PAD + AT_SQ * AT_PPAD + 3 * AT_SQ)

__global__ __launch_bounds__(256)
void attn_window(const float* __restrict__ Q, const float* __restrict__ Km,
                 const float* __restrict__ Vm, float* __restrict__ O)
{
    extern __shared__ float sm[];
    float* Qs  = sm;                          // [64][129]
    float* KVs = Qs + AT_SQ * AT_PAD;         // [64][129]  (K, then reused for V)
    float* Ps  = KVs + AT_CK * AT_PAD;        // [64][65]
    float* mS  = Ps + AT_SQ * AT_PPAD;        // [64] running max
    float* sS  = mS + AT_SQ;                  // [64] running sum
    float* fS  = sS + AT_SQ;                  // [64] rescale factor this chunk

    const int t  = threadIdx.x;
    const int q0 = blockIdx.x * AT_SQ;
    const int h  = blockIdx.y;
    const int b  = blockIdx.z;
    const int tq = t >> 4;    // 0..15
    const int tk = t & 15;    // 0..15

    // load Q tile
    const float* Qg = Q + ((size_t)(b * S_LEN + q0)) * D_MODEL + h * HDIM;
    for (int i = t; i < AT_SQ * (HDIM / 4); i += 256) {
        int r = i >> 5, c = (i & 31) << 2;
        float4 v4 = *(const float4*)(Qg + (size_t)r * D_MODEL + c);
        float* d = Qs + r * AT_PAD + c;
        d[0] = v4.x; d[1] = v4.y; d[2] = v4.z; d[3] = v4.w;
    }
    if (t < AT_SQ) { mS[t] = -1e30f; sS[t] = 0.0f; }

    float oacc[4][8];
#pragma unroll
    for (int j = 0; j < 4; j++)
#pragma unroll
        for (int i = 0; i < 8; i++) oacc[j][i] = 0.0f;
    __syncthreads();

    const float scale = 0.088388347648318447f;  // 1/sqrt(128)

    for (int c0 = 0; c0 < q0 + AT_SQ; c0 += AT_CK) {
        // chunk needed if it can contain a sink key or any in-window key
        if (!((c0 < PERSIST) || (c0 + AT_CK - 1 >= q0 - (WINDOW - 1)))) continue;

        // ---- load K chunk ----
        const float* Kg = Km + ((size_t)(b * S_LEN + c0)) * D_MODEL + h * HDIM;
        for (int i = t; i < AT_CK * (HDIM / 4); i += 256) {
            int r = i >> 5, c = (i & 31) << 2;
            float4 v4 = *(const float4*)(Kg + (size_t)r * D_MODEL + c);
            float* d = KVs + r * AT_PAD + c;
            d[0] = v4.x; d[1] = v4.y; d[2] = v4.z; d[3] = v4.w;
        }
        __syncthreads();

        // ---- scores: thread owns q rows {tq+16j}, k cols {tk+16i} ----
        float sc[4][4];
#pragma unroll
        for (int j = 0; j < 4; j++)
#pragma unroll
            for (int i = 0; i < 4; i++) sc[j][i] = 0.0f;

        const float* qp0 = Qs + (tq +  0) * AT_PAD;
        const float* qp1 = Qs + (tq + 16) * AT_PAD;
        const float* qp2 = Qs + (tq + 32) * AT_PAD;
        const float* qp3 = Qs + (tq + 48) * AT_PAD;
        const float* kp0 = KVs + (tk +  0) * AT_PAD;
        const float* kp1 = KVs + (tk + 16) * AT_PAD;
        const float* kp2 = KVs + (tk + 32) * AT_PAD;
        const float* kp3 = KVs + (tk + 48) * AT_PAD;
#pragma unroll 4
        for (int d = 0; d < HDIM; d++) {
            float a0 = qp0[d], a1 = qp1[d], a2 = qp2[d], a3 = qp3[d];
            float b0 = kp0[d], b1 = kp1[d], b2 = kp2[d], b3 = kp3[d];
            sc[0][0] += a0 * b0; sc[0][1] += a0 * b1; sc[0][2] += a0 * b2; sc[0][3] += a0 * b3;
            sc[1][0] += a1 * b0; sc[1][1] += a1 * b1; sc[1][2] += a1 * b2; sc[1][3] += a1 * b3;
            sc[2][0] += a2 * b0; sc[2][1] += a2 * b1; sc[2][2] += a2 * b2; sc[2][3] += a2 * b3;
            sc[3][0] += a3 * b0; sc[3][1] += a3 * b1; sc[3][2] += a3 * b2; sc[3][3] += a3 * b3;
        }

        // ---- mask, online-softmax state update, write P ----
#pragma unroll
        for (int j = 0; j < 4; j++) {
            const int row = tq + 16 * j;
            const int qg  = q0 + row;
            float mloc = -1e30f;
#pragma unroll
            for (int i = 0; i < 4; i++) {
                int kg = c0 + tk + 16 * i;
                bool valid = (kg <= qg) && ((qg - kg < WINDOW) || (kg < PERSIST));
                sc[j][i] = valid ? sc[j][i] * scale : -1e30f;
                mloc = fmaxf(mloc, sc[j][i]);
            }
#pragma unroll
            for (int off = 8; off > 0; off >>= 1)
                mloc = fmaxf(mloc, __shfl_xor_sync(0xffffffffu, mloc, off));

            float mold = mS[row];
            float mnew = fmaxf(mold, mloc);
            float p[4];
            float sloc = 0.0f;
#pragma unroll
            for (int i = 0; i < 4; i++) {
                p[i] = (sc[j][i] > -1e29f) ? __expf(sc[j][i] - mnew) : 0.0f;
                sloc += p[i];
            }
#pragma unroll
            for (int off = 8; off > 0; off >>= 1)
                sloc += __shfl_xor_sync(0xffffffffu, sloc, off);

            if (tk == 0) {
                float f = __expf(mold - mnew);
                sS[row] = sS[row] * f + sloc;
                mS[row] = mnew;
                fS[row] = f;
            }
#pragma unroll
            for (int i = 0; i < 4; i++)
                Ps[row * AT_PPAD + tk + 16 * i] = p[i];
        }
        __syncthreads();

        // ---- load V chunk (reuse KVs) ----
        const float* Vg = Vm + ((size_t)(b * S_LEN + c0)) * D_MODEL + h * HDIM;
        for (int i = t; i < AT_CK * (HDIM / 4); i += 256) {
            int r = i >> 5, c = (i & 31) << 2;
            float4 v4 = *(const float4*)(Vg + (size_t)r * D_MODEL + c);
            float* d = KVs + r * AT_PAD + c;
            d[0] = v4.x; d[1] = v4.y; d[2] = v4.z; d[3] = v4.w;
        }
        __syncthreads();

        // ---- O += P @ V : thread owns q rows {tq+16j}, d cols {tk+16i} ----
        {
            float f0 = fS[tq +  0], f1 = fS[tq + 16], f2 = fS[tq + 32], f3 = fS[tq + 48];
#pragma unroll
            for (int i = 0; i < 8; i++) {
                oacc[0][i] *= f0; oacc[1][i] *= f1; oacc[2][i] *= f2; oacc[3][i] *= f3;
            }
            const float* pp0 = Ps + (tq +  0) * AT_PPAD;
            const float* pp1 = Ps + (tq + 16) * AT_PPAD;
            const float* pp2 = Ps + (tq + 32) * AT_PPAD;
            const float* pp3 = Ps + (tq + 48) * AT_PPAD;
#pragma unroll 2
            for (int kk = 0; kk < AT_CK; kk++) {
                float p0 = pp0[kk], p1 = pp1[kk], p2 = pp2[kk], p3 = pp3[kk];
                const float* vrow = KVs + kk * AT_PAD + tk;
#pragma unroll
                for (int i = 0; i < 8; i++) {
                    float vv = vrow[16 * i];
                    oacc[0][i] += p0 * vv;
                    oacc[1][i] += p1 * vv;
                    oacc[2][i] += p2 * vv;
                    oacc[3][i] += p3 * vv;
                }
            }
        }
        __syncthreads();   // protect Ps/KVs for next chunk
    }

    // ---- normalize + write ----
#pragma unroll
    for (int j = 0; j < 4; j++) {
        const int row = tq + 16 * j;
        const int qg  = q0 + row;
        float inv = 1.0f / sS[row];
        float* orow = O + ((size_t)(b * S_LEN + qg)) * D_MODEL + h * HDIM;
#pragma unroll
        for (int i = 0; i < 8; i++)
            orow[tk + 16 * i] = oacc[j][i] * inv;
    }
}

// ---------------------------------------------------------------------------
// Launch: 5 GEMMs + attention, all graph-capturable, allocation-free.
// ---------------------------------------------------------------------------
extern "C" void kernel_launch(void* const* d_in, const int* in_sizes, int n_in,
                              void* d_out, int out_size)
{
    const float* x   = (const float*)d_in[0];
    const float* Wq  = (const float*)d_in[1];
    const float* Wkv = (const float*)d_in[2];
    const float* Wk  = (const float*)d_in[3];
    const float* Wv  = (const float*)d_in[4];
    const float* Wo  = (const float*)d_in[5];
    float* out = (float*)d_out;

    float *Qb, *KVb, *Kb, *Vb, *AOb;
    cudaGetSymbolAddress((void**)&Qb,  g_Q);
    cudaGetSymbolAddress((void**)&KVb, g_KV);
    cudaGetSymbolAddress((void**)&Kb,  g_K);
    cudaGetSymbolAddress((void**)&Vb,  g_V);
    cudaGetSymbolAddress((void**)&AOb, g_AO);

    const int asmem = AT_SMEM_FLOATS * (int)sizeof(float);
    cudaFuncSetAttribute((const void*)attn_window,
                         cudaFuncAttributeMaxDynamicSharedMemorySize, asmem);

    dim3 blk(256);
    // Q = X @ Wq                       [4096,2048] = [4096,2048]@[2048,2048]
    sgemm128x128<<<dim3(D_MODEL / 128, M_ROWS / 128), blk>>>(x, Wq, Qb, M_ROWS, D_MODEL, D_MODEL);
    // KV = X @ Wkv                     [4096,512]  = [4096,2048]@[2048,512]
    sgemm128x128<<<dim3(L_LAT / 128, M_ROWS / 128), blk>>>(x, Wkv, KVb, M_ROWS, L_LAT, D_MODEL);
    // K = KV @ Wk                      [4096,2048] = [4096,512]@[512,2048]
    sgemm128x128<<<dim3(D_MODEL / 128, M_ROWS / 128), blk>>>(KVb, Wk, Kb, M_ROWS, D_MODEL, L_LAT);
    // V = KV @ Wv
    sgemm128x128<<<dim3(D_MODEL / 128, M_ROWS / 128), blk>>>(KVb, Wv, Vb, M_ROWS, D_MODEL, L_LAT);
    // windowed attention
    attn_window<<<dim3(S_LEN / AT_SQ, NHEADS, BATCH), blk, asmem>>>(Qb, Kb, Vb, AOb);
    // OUT = AO @ Wo
    sgemm128x128<<<dim3(D_MODEL / 128, M_ROWS / 128), blk>>>(AOb, Wo, out, M_ROWS, D_MODEL, D_MODEL);
}

// round 3
// speedup vs baseline: 2.4090x; 2.4090x over previous
#include <cuda_runtime.h>
#include <cuda_bf16.h>
#include <cstdint>
#include <math.h>

// ---------------------------------------------------------------------------
// Problem constants
// ---------------------------------------------------------------------------
#define S_LEN   2048
#define D_MODEL 2048
#define L_LAT   512
#define BATCH   2
#define NHEADS  16
#define HDIM    128
#define M_ROWS  (BATCH * S_LEN)   // 4096
#define WINDOW  128
#define PERSIST 16

// ---------------------------------------------------------------------------
// PTX helpers (portable: ldmatrix / mma.sync / cp.async — all legal on sm_103)
// ---------------------------------------------------------------------------
__device__ __forceinline__ uint32_t smem_u32(const void* p) {
    uint32_t a;
    asm("{ .reg .u64 t; cvta.to.shared.u64 t, %1; cvt.u32.u64 %0, t; }"
        : "=r"(a) : "l"(p));
    return a;
}

__device__ __forceinline__ void ldsm4(uint32_t* r, uint32_t addr) {
    asm volatile("ldmatrix.sync.aligned.m8n8.x4.shared.b16 {%0,%1,%2,%3}, [%4];"
                 : "=r"(r[0]), "=r"(r[1]), "=r"(r[2]), "=r"(r[3]) : "r"(addr));
}

__device__ __forceinline__ void mma16816(float* c, const uint32_t* a, const uint32_t* b) {
    asm volatile("mma.sync.aligned.m16n8k16.row.col.f32.bf16.bf16.f32 "
                 "{%0,%1,%2,%3}, {%4,%5,%6,%7}, {%8,%9}, {%0,%1,%2,%3};"
                 : "+f"(c[0]), "+f"(c[1]), "+f"(c[2]), "+f"(c[3])
                 : "r"(a[0]), "r"(a[1]), "r"(a[2]), "r"(a[3]),
                   "r"(b[0]), "r"(b[1]));
}

#define CP_ASYNC16(s, g) \
    asm volatile("cp.async.cg.shared.global [%0], [%1], 16;" :: "r"(s), "l"(g))
#define CP_COMMIT() asm volatile("cp.async.commit_group;" ::: "memory")
#define CP_WAIT0()  asm volatile("cp.async.wait_group 0;" ::: "memory")

// ---------------------------------------------------------------------------
// Scratch buffers (static __device__ — no allocation allowed)
// ---------------------------------------------------------------------------
__device__ float g_Q [(size_t)M_ROWS * D_MODEL];
__device__ float g_K [(size_t)M_ROWS * D_MODEL];
__device__ float g_V [(size_t)M_ROWS * D_MODEL];
__device__ float g_KV[(size_t)M_ROWS * L_LAT];
__device__ float g_AO[(size_t)M_ROWS * D_MODEL];

#define N_XD   ((size_t)M_ROWS * D_MODEL)
#define N_DD   ((size_t)D_MODEL * D_MODEL)
#define N_DL   ((size_t)D_MODEL * L_LAT)
#define N_ML   ((size_t)M_ROWS * L_LAT)

__device__ __nv_bfloat16 g_xh [N_XD];
__device__ __nv_bfloat16 g_xl [N_XD];
__device__ __nv_bfloat16 g_WqTh[N_DD];
__device__ __nv_bfloat16 g_WqTl[N_DD];
__device__ __nv_bfloat16 g_WkvTh[N_DL];
__device__ __nv_bfloat16 g_WkvTl[N_DL];
__device__ __nv_bfloat16 g_WkTh[N_DL];
__device__ __nv_bfloat16 g_WkTl[N_DL];
__device__ __nv_bfloat16 g_WvTh[N_DL];
__device__ __nv_bfloat16 g_WvTl[N_DL];
__device__ __nv_bfloat16 g_WoTh[N_DD];
__device__ __nv_bfloat16 g_WoTl[N_DD];
__device__ __nv_bfloat16 g_KVh[N_ML];
__device__ __nv_bfloat16 g_KVl[N_ML];
__device__ __nv_bfloat16 g_AOh[N_XD];
__device__ __nv_bfloat16 g_AOl[N_XD];

// ---------------------------------------------------------------------------
// fp32 -> bf16 hi/lo split, row-major
// ---------------------------------------------------------------------------
__global__ void split_rows(const float4* __restrict__ in,
                           __nv_bfloat162* __restrict__ oh,
                           __nv_bfloat162* __restrict__ ol, int n4)
{
    int i = blockIdx.x * blockDim.x + threadIdx.x;
    if (i >= n4) return;
    float4 v = in[i];
    __nv_bfloat16 h0 = __float2bfloat16(v.x);
    __nv_bfloat16 h1 = __float2bfloat16(v.y);
    __nv_bfloat16 h2 = __float2bfloat16(v.z);
    __nv_bfloat16 h3 = __float2bfloat16(v.w);
    __nv_bfloat16 l0 = __float2bfloat16(v.x - __bfloat162float(h0));
    __nv_bfloat16 l1 = __float2bfloat16(v.y - __bfloat162float(h1));
    __nv_bfloat16 l2 = __float2bfloat16(v.z - __bfloat162float(h2));
    __nv_bfloat16 l3 = __float2bfloat16(v.w - __bfloat162float(h3));
    oh[2 * i]     = __halves2bfloat162(h0, h1);
    oh[2 * i + 1] = __halves2bfloat162(h2, h3);
    ol[2 * i]     = __halves2bfloat162(l0, l1);
    ol[2 * i + 1] = __halves2bfloat162(l2, l3);
}

// Transpose + split: in [R,C] fp32 -> out [C,R] bf16 hi/lo
__global__ void split_transpose(const float* __restrict__ in,
                                __nv_bfloat16* __restrict__ oh,
                                __nv_bfloat16* __restrict__ ol, int R, int C)
{
    __shared__ float tile[32][33];
    int c0 = blockIdx.x * 32, r0 = blockIdx.y * 32;
    int tx = threadIdx.x, ty = threadIdx.y;
#pragma unroll
    for (int j = 0; j < 32; j += 8)
        tile[ty + j][tx] = in[(size_t)(r0 + ty + j) * C + c0 + tx];
    __syncthreads();
#pragma unroll
    for (int j = 0; j < 32; j += 8) {
        float v = tile[tx][ty + j];
        __nv_bfloat16 h = __float2bfloat16(v);
        __nv_bfloat16 l = __float2bfloat16(v - __bfloat162float(h));
        size_t o = (size_t)(c0 + ty + j) * R + r0 + tx;
        oh[o] = h;
        ol[o] = l;
    }
}

// ---------------------------------------------------------------------------
// HMMA split-bf16 GEMM: C[M,N] = A[M,K] @ B[K,N], B given transposed Bt[N,K].
// A as (Ah, Al), Bt as (Bh, Bl). Tile 128x128, BK=64, 256 threads (8 warps,
// 2x4 grid, 64x32 per warp), SW128-swizzled smem, cp.async double buffer.
// ---------------------------------------------------------------------------
#define GT_BYTES    (128 * 64 * 2)     // one 128x64 bf16 tile = 16 KB
#define GSTAGE      (4 * GT_BYTES)     // Ah, Al, Bh, Bl      = 64 KB
#define GSMEM_TOTAL (2 * GSTAGE)       // double buffered     = 128 KB

// load one 128x64 bf16 tile (rows of 128B) into swizzled smem via cp.async
__device__ __forceinline__ void stage_tile(uint32_t sdst,
                                           const __nv_bfloat16* __restrict__ g,
                                           int ldK, int t)
{
#pragma unroll
    for (int j = 0; j < 4; j++) {
        int id = t + 256 * j;
        int r = id >> 3, c = id & 7;
        uint32_t off = (uint32_t)(r * 128 + c * 16);
        off ^= (off >> 3) & 0x70;
        CP_ASYNC16(sdst + off, g + (size_t)r * ldK + c * 8);
    }
}

__global__ __launch_bounds__(256, 1)
void gemm_mma(const __nv_bfloat16* __restrict__ Ah, const __nv_bfloat16* __restrict__ Al,
              const __nv_bfloat16* __restrict__ Bh, const __nv_bfloat16* __restrict__ Bl,
              float* __restrict__ C, int Mdim, int Ndim, int Kdim)
{
    extern __shared__ char smc[];
    const uint32_t sb = smem_u32(smc);
    const int t    = threadIdx.x;
    const int lane = t & 31;
    const int w    = t >> 5;
    const int bm   = blockIdx.y * 128;
    const int bn   = blockIdx.x * 128;
    const int m0   = (w >> 2) * 64;    // warp M offset in tile
    const int n0   = (w & 3) * 32;     // warp N offset in tile

    const __nv_bfloat16* Ahp = Ah + (size_t)bm * Kdim;
    const __nv_bfloat16* Alp = Al + (size_t)bm * Kdim;
    const __nv_bfloat16* Bhp = Bh + (size_t)bn * Kdim;
    const __nv_bfloat16* Blp = Bl + (size_t)bn * Kdim;

    // ldmatrix lane geometry (swizzle mask depends only on row%8 == lane%8)
    const uint32_t mask = (uint32_t)((lane & 7) << 4);
    const uint32_t akx  = (uint32_t)(((lane >> 4) & 1) * 16);  // A: mat>>1 -> k+8
    const uint32_t bkx  = (uint32_t)(((lane >> 3) & 1) * 16);  // B: mat&1  -> k+8
    uint32_t arow[4], brow[2];
#pragma unroll
    for (int mt = 0; mt < 4; mt++)
        arow[mt] = (uint32_t)((m0 + 16 * mt + (lane & 7) + ((lane >> 3) & 1) * 8) * 128);
#pragma unroll
    for (int p = 0; p < 2; p++)
        brow[p] = (uint32_t)((n0 + 16 * p + (lane & 7) + ((lane >> 4) & 1) * 8) * 128);

    float acc[4][4][4];
#pragma unroll
    for (int mt = 0; mt < 4; mt++)
#pragma unroll
        for (int nt = 0; nt < 4; nt++)
#pragma unroll
            for (int i = 0; i < 4; i++) acc[mt][nt][i] = 0.0f;

    const int nch = Kdim >> 6;

    // prologue: stage chunk 0 into buffer 0
    stage_tile(sb + 0 * GT_BYTES, Ahp, Kdim, t);
    stage_tile(sb + 1 * GT_BYTES, Alp, Kdim, t);
    stage_tile(sb + 2 * GT_BYTES, Bhp, Kdim, t);
    stage_tile(sb + 3 * GT_BYTES, Blp, Kdim, t);
    CP_COMMIT();

    for (int c = 0; c < nch; ++c) {
        CP_WAIT0();
        __syncthreads();

        if (c + 1 < nch) {
            uint32_t nbase = sb + (uint32_t)(((c + 1) & 1) * GSTAGE);
            size_t ko = (size_t)(c + 1) * 64;
            stage_tile(nbase + 0 * GT_BYTES, Ahp + ko, Kdim, t);
            stage_tile(nbase + 1 * GT_BYTES, Alp + ko, Kdim, t);
            stage_tile(nbase + 2 * GT_BYTES, Bhp + ko, Kdim, t);
            stage_tile(nbase + 3 * GT_BYTES, Blp + ko, Kdim, t);
            CP_COMMIT();
        }

        const uint32_t base = sb + (uint32_t)((c & 1) * GSTAGE);
        const uint32_t sAh = base + 0 * GT_BYTES;
        const uint32_t sAl = base + 1 * GT_BYTES;
        const uint32_t sBh = base + 2 * GT_BYTES;
        const uint32_t sBl = base + 3 * GT_BYTES;

#pragma unroll
        for (int s = 0; s < 4; s++) {
            const uint32_t kb = (uint32_t)(32 * s);
            const uint32_t ka = (kb + akx) ^ mask;
            const uint32_t kB = (kb + bkx) ^ mask;

            uint32_t ah[4][4], al[4][4], bh[4][2], bl[4][2];
#pragma unroll
            for (int mt = 0; mt < 4; mt++) {
                ldsm4(ah[mt], sAh + arow[mt] + ka);
                ldsm4(al[mt], sAl + arow[mt] + ka);
            }
#pragma unroll
            for (int p = 0; p < 2; p++) {
                uint32_t r[4];
                ldsm4(r, sBh + brow[p] + kB);
                bh[2 * p][0] = r[0]; bh[2 * p][1] = r[1];
                bh[2 * p + 1][0] = r[2]; bh[2 * p + 1][1] = r[3];
                ldsm4(r, sBl + brow[p] + kB);
                bl[2 * p][0] = r[0]; bl[2 * p][1] = r[1];
                bl[2 * p + 1][0] = r[2]; bl[2 * p + 1][1] = r[3];
            }
#pragma unroll
            for (int mt = 0; mt < 4; mt++)
#pragma unroll
                for (int nt = 0; nt < 4; nt++) {
                    mma16816(acc[mt][nt], ah[mt], bh[nt]);
                    mma16816(acc[mt][nt], ah[mt], bl[nt]);
                    mma16816(acc[mt][nt], al[mt], bh[nt]);
                }
        }
    }

    // epilogue: write fp32 C
    const int rbase = bm + m0 + (lane >> 2);
    const int cbase = bn + n0 + (lane & 3) * 2;
#pragma unroll
    for (int mt = 0; mt < 4; mt++)
#pragma unroll
        for (int nt = 0; nt < 4; nt++) {
            float* p0 = C + (size_t)(rbase + 16 * mt) * Ndim + cbase + 8 * nt;
            float* p1 = p0 + (size_t)8 * Ndim;
            *(float2*)p0 = make_float2(acc[mt][nt][0], acc[mt][nt][1]);
            *(float2*)p1 = make_float2(acc[mt][nt][2], acc[mt][nt][3]);
        }
}

// ---------------------------------------------------------------------------
// Windowed causal attention with persistent sink (fp32, unchanged)
// ---------------------------------------------------------------------------
#define AT_SQ   64
#define AT_CK   64
#define AT_PAD  129
#define AT_PPAD 65
#define AT_SMEM_FLOATS (AT_SQ * AT_PAD + AT_CK * AT_PAD + AT_SQ * AT_PPAD + 3 * AT_SQ)

__global__ __launch_bounds__(256)
void attn_window(const float* __restrict__ Q, const float* __restrict__ Km,
                 const float* __restrict__ Vm, float* __restrict__ O)
{
    extern __shared__ float smf[];
    float* Qs  = smf;
    float* KVs = Qs + AT_SQ * AT_PAD;
    float* Ps  = KVs + AT_CK * AT_PAD;
    float* mS  = Ps + AT_SQ * AT_PPAD;
    float* sS  = mS + AT_SQ;
    float* fS  = sS + AT_SQ;

    const int t  = threadIdx.x;
    const int q0 = blockIdx.x * AT_SQ;
    const int h  = blockIdx.y;
    const int b  = blockIdx.z;
    const int tq = t >> 4;
    const int tk = t & 15;

    const float* Qg = Q + ((size_t)(b * S_LEN + q0)) * D_MODEL + h * HDIM;
    for (int i = t; i < AT_SQ * (HDIM / 4); i += 256) {
        int r = i >> 5, c = (i & 31) << 2;
        float4 v4 = *(const float4*)(Qg + (size_t)r * D_MODEL + c);
        float* d = Qs + r * AT_PAD + c;
        d[0] = v4.x; d[1] = v4.y; d[2] = v4.z; d[3] = v4.w;
    }
    if (t < AT_SQ) { mS[t] = -1e30f; sS[t] = 0.0f; }

    float oacc[4][8];
#pragma unroll
    for (int j = 0; j < 4; j++)
#pragma unroll
        for (int i = 0; i < 8; i++) oacc[j][i] = 0.0f;
    __syncthreads();

    const float scale = 0.088388347648318447f;

    for (int c0 = 0; c0 < q0 + AT_SQ; c0 += AT_CK) {
        if (!((c0 < PERSIST) || (c0 + AT_CK - 1 >= q0 - (WINDOW - 1)))) continue;

        const float* Kg = Km + ((size_t)(b * S_LEN + c0)) * D_MODEL + h * HDIM;
        for (int i = t; i < AT_CK * (HDIM / 4); i += 256) {
            int r = i >> 5, c = (i & 31) << 2;
            float4 v4 = *(const float4*)(Kg + (size_t)r * D_MODEL + c);
            float* d = KVs + r * AT_PAD + c;
            d[0] = v4.x; d[1] = v4.y; d[2] = v4.z; d[3] = v4.w;
        }
        __syncthreads();

        float sc[4][4];
#pragma unroll
        for (int j = 0; j < 4; j++)
#pragma unroll
            for (int i = 0; i < 4; i++) sc[j][i] = 0.0f;

        const float* qp0 = Qs + (tq +  0) * AT_PAD;
        const float* qp1 = Qs + (tq + 16) * AT_PAD;
        const float* qp2 = Qs + (tq + 32) * AT_PAD;
        const float* qp3 = Qs + (tq + 48) * AT_PAD;
        const float* kp0 = KVs + (tk +  0) * AT_PAD;
        const float* kp1 = KVs + (tk + 16) * AT_PAD;
        const float* kp2 = KVs + (tk + 32) * AT_PAD;
        const float* kp3 = KVs + (tk + 48) * AT_PAD;
#pragma unroll 4
        for (int d = 0; d < HDIM; d++) {
            float a0 = qp0[d], a1 = qp1[d], a2 = qp2[d], a3 = qp3[d];
            float b0 = kp0[d], b1 = kp1[d], b2 = kp2[d], b3 = kp3[d];
            sc[0][0] += a0 * b0; sc[0][1] += a0 * b1; sc[0][2] += a0 * b2; sc[0][3] += a0 * b3;
            sc[1][0] += a1 * b0; sc[1][1] += a1 * b1; sc[1][2] += a1 * b2; sc[1][3] += a1 * b3;
            sc[2][0] += a2 * b0; sc[2][1] += a2 * b1; sc[2][2] += a2 * b2; sc[2][3] += a2 * b3;
            sc[3][0] += a3 * b0; sc[3][1] += a3 * b1; sc[3][2] += a3 * b2; sc[3][3] += a3 * b3;
        }

#pragma unroll
        for (int j = 0; j < 4; j++) {
            const int row = tq + 16 * j;
            const int qg  = q0 + row;
            float mloc = -1e30f;
#pragma unroll
            for (int i = 0; i < 4; i++) {
                int kg = c0 + tk + 16 * i;
                bool valid = (kg <= qg) && ((qg - kg < WINDOW) || (kg < PERSIST));
                sc[j][i] = valid ? sc[j][i] * scale : -1e30f;
                mloc = fmaxf(mloc, sc[j][i]);
            }
#pragma unroll
            for (int off = 8; off > 0; off >>= 1)
                mloc = fmaxf(mloc, __shfl_xor_sync(0xffffffffu, mloc, off));

            float mold = mS[row];
            float mnew = fmaxf(mold, mloc);
            float p[4];
            float sloc = 0.0f;
#pragma unroll
            for (int i = 0; i < 4; i++) {
                p[i] = (sc[j][i] > -1e29f) ? __expf(sc[j][i] - mnew) : 0.0f;
                sloc += p[i];
            }
#pragma unroll
            for (int off = 8; off > 0; off >>= 1)
                sloc += __shfl_xor_sync(0xffffffffu, sloc, off);

            if (tk == 0) {
                float f = __expf(mold - mnew);
                sS[row] = sS[row] * f + sloc;
                mS[row] = mnew;
                fS[row] = f;
            }
#pragma unroll
            for (int i = 0; i < 4; i++)
                Ps[row * AT_PPAD + tk + 16 * i] = p[i];
        }
        __syncthreads();

        const float* Vg = Vm + ((size_t)(b * S_LEN + c0)) * D_MODEL + h * HDIM;
        for (int i = t; i < AT_CK * (HDIM / 4); i += 256) {
            int r = i >> 5, c = (i & 31) << 2;
            float4 v4 = *(const float4*)(Vg + (size_t)r * D_MODEL + c);
            float* d = KVs + r * AT_PAD + c;
            d[0] = v4.x; d[1] = v4.y; d[2] = v4.z; d[3] = v4.w;
        }
        __syncthreads();

        {
            float f0 = fS[tq +  0], f1 = fS[tq + 16], f2 = fS[tq + 32], f3 = fS[tq + 48];
#pragma unroll
            for (int i = 0; i < 8; i++) {
                oacc[0][i] *= f0; oacc[1][i] *= f1; oacc[2][i] *= f2; oacc[3][i] *= f3;
            }
            const float* pp0 = Ps + (tq +  0) * AT_PPAD;
            const float* pp1 = Ps + (tq + 16) * AT_PPAD;
            const float* pp2 = Ps + (tq + 32) * AT_PPAD;
            const float* pp3 = Ps + (tq + 48) * AT_PPAD;
#pragma unroll 2
            for (int kk = 0; kk < AT_CK; kk++) {
                float p0 = pp0[kk], p1 = pp1[kk], p2 = pp2[kk], p3 = pp3[kk];
                const float* vrow = KVs + kk * AT_PAD + tk;
#pragma unroll
                for (int i = 0; i < 8; i++) {
                    float vv = vrow[16 * i];
                    oacc[0][i] += p0 * vv;
                    oacc[1][i] += p1 * vv;
                    oacc[2][i] += p2 * vv;
                    oacc[3][i] += p3 * vv;
                }
            }
        }
        __syncthreads();
    }

#pragma unroll
    for (int j = 0; j < 4; j++) {
        const int row = tq + 16 * j;
        const int qg  = q0 + row;
        float inv = 1.0f / sS[row];
        float* orow = O + ((size_t)(b * S_LEN + qg)) * D_MODEL + h * HDIM;
#pragma unroll
        for (int i = 0; i < 8; i++)
            orow[tk + 16 * i] = oacc[j][i] * inv;
    }
}

// ---------------------------------------------------------------------------
// Launch
// ---------------------------------------------------------------------------
extern "C" void kernel_launch(void* const* d_in, const int* in_sizes, int n_in,
                              void* d_out, int out_size)
{
    const float* x   = (const float*)d_in[0];
    const float* Wq  = (const float*)d_in[1];
    const float* Wkv = (const float*)d_in[2];
    const float* Wk  = (const float*)d_in[3];
    const float* Wv  = (const float*)d_in[4];
    const float* Wo  = (const float*)d_in[5];
    float* out = (float*)d_out;

    float *Qb, *Kb, *Vb, *KVb, *AOb;
    cudaGetSymbolAddress((void**)&Qb,  g_Q);
    cudaGetSymbolAddress((void**)&Kb,  g_K);
    cudaGetSymbolAddress((void**)&Vb,  g_V);
    cudaGetSymbolAddress((void**)&KVb, g_KV);
    cudaGetSymbolAddress((void**)&AOb, g_AO);

    __nv_bfloat16 *xh, *xl, *WqTh, *WqTl, *WkvTh, *WkvTl, *WkTh, *WkTl,
                  *WvTh, *WvTl, *WoTh, *WoTl, *KVh, *KVl, *AOh, *AOl;
    cudaGetSymbolAddress((void**)&xh,   g_xh);
    cudaGetSymbolAddress((void**)&xl,   g_xl);
    cudaGetSymbolAddress((void**)&WqTh, g_WqTh);
    cudaGetSymbolAddress((void**)&WqTl, g_WqTl);
    cudaGetSymbolAddress((void**)&WkvTh, g_WkvTh);
    cudaGetSymbolAddress((void**)&WkvTl, g_WkvTl);
    cudaGetSymbolAddress((void**)&WkTh, g_WkTh);
    cudaGetSymbolAddress((void**)&WkTl, g_WkTl);
    cudaGetSymbolAddress((void**)&WvTh, g_WvTh);
    cudaGetSymbolAddress((void**)&WvTl, g_WvTl);
    cudaGetSymbolAddress((void**)&WoTh, g_WoTh);
    cudaGetSymbolAddress((void**)&WoTl, g_WoTl);
    cudaGetSymbolAddress((void**)&KVh,  g_KVh);
    cudaGetSymbolAddress((void**)&KVl,  g_KVl);
    cudaGetSymbolAddress((void**)&AOh,  g_AOh);
    cudaGetSymbolAddress((void**)&AOl,  g_AOl);

    cudaFuncSetAttribute((const void*)gemm_mma,
                         cudaFuncAttributeMaxDynamicSharedMemorySize, GSMEM_TOTAL);
    const int asmem = AT_SMEM_FLOATS * (int)sizeof(float);
    cudaFuncSetAttribute((const void*)attn_window,
                         cudaFuncAttributeMaxDynamicSharedMemorySize, asmem);

    // input conversions
    {
        int n4 = (int)(N_XD / 4);
        split_rows<<<(n4 + 255) / 256, 256>>>((const float4*)x,
                                              (__nv_bfloat162*)xh, (__nv_bfloat162*)xl, n4);
    }
    split_transpose<<<dim3(D_MODEL / 32, D_MODEL / 32), dim3(32, 8)>>>(Wq,  WqTh,  WqTl,  D_MODEL, D_MODEL);
    split_transpose<<<dim3(L_LAT  / 32, D_MODEL / 32), dim3(32, 8)>>>(Wkv, WkvTh, WkvTl, D_MODEL, L_LAT);
    split_transpose<<<dim3(D_MODEL / 32, L_LAT  / 32), dim3(32, 8)>>>(Wk,  WkTh,  WkTl,  L_LAT,  D_MODEL);
    split_transpose<<<dim3(D_MODEL / 32, L_LAT  / 32), dim3(32, 8)>>>(Wv,  WvTh,  WvTl,  L_LAT,  D_MODEL);
    split_transpose<<<dim3(D_MODEL / 32, D_MODEL / 32), dim3(32, 8)>>>(Wo,  WoTh,  WoTl,  D_MODEL, D_MODEL);

    // Q = x @ Wq
    gemm_mma<<<dim3(D_MODEL / 128, M_ROWS / 128), 256, GSMEM_TOTAL>>>(
        xh, xl, WqTh, WqTl, Qb, M_ROWS, D_MODEL, D_MODEL);
    // KV = x @ Wkv
    gemm_mma<<<dim3(L_LAT / 128, M_ROWS / 128), 256, GSMEM_TOTAL>>>(
        xh, xl, WkvTh, WkvTl, KVb, M_ROWS, L_LAT, D_MODEL);
    // split KV
    {
        int n4 = (int)(N_ML / 4);
        split_rows<<<(n4 + 255) / 256, 256>>>((const float4*)KVb,
                                              (__nv_bfloat162*)KVh, (__nv_bfloat162*)KVl, n4);
    }
    // K = KV @ Wk ; V = KV @ Wv
    gemm_mma<<<dim3(D_MODEL / 128, M_ROWS / 128), 256, GSMEM_TOTAL>>>(
        KVh, KVl, WkTh, WkTl, Kb, M_ROWS, D_MODEL, L_LAT);
    gemm_mma<<<dim3(D_MODEL / 128, M_ROWS / 128), 256, GSMEM_TOTAL>>>(
        KVh, KVl, WvTh, WvTl, Vb, M_ROWS, D_MODEL, L_LAT);
    // attention
    attn_window<<<dim3(S_LEN / AT_SQ, NHEADS, BATCH), 256, asmem>>>(Qb, Kb, Vb, AOb);
    // split AO
    {
        int n4 = (int)(N_XD / 4);
        split_rows<<<(n4 + 255) / 256, 256>>>((const float4*)AOb,
                                              (__nv_bfloat162*)AOh, (__nv_bfloat162*)AOl, n4);
    }
    // out = AO @ Wo
    gemm_mma<<<dim3(D_MODEL / 128, M_ROWS / 128), 256, GSMEM_TOTAL>>>(
        AOh, AOl, WoTh, WoTl, out, M_ROWS, D_MODEL, D_MODEL);
}

// round 4
// speedup vs baseline: 3.0840x; 1.2802x over previous
#include <cuda_runtime.h>
#include <cuda_bf16.h>
#include <cstdint>
#include <math.h>

// ---------------------------------------------------------------------------
// Problem constants
// ---------------------------------------------------------------------------
#define S_LEN   2048
#define D_MODEL 2048
#define L_LAT   512
#define BATCH   2
#define NHEADS  16
#define HDIM    128
#define M_ROWS  (BATCH * S_LEN)   // 4096
#define WINDOW  128
#define PERSIST 16

// ---------------------------------------------------------------------------
// PTX helpers (portable on sm_103: ldmatrix / mma.sync / cp.async)
// ---------------------------------------------------------------------------
__device__ __forceinline__ uint32_t smem_u32(const void* p) {
    uint32_t a;
    asm("{ .reg .u64 t; cvta.to.shared.u64 t, %1; cvt.u32.u64 %0, t; }"
        : "=r"(a) : "l"(p));
    return a;
}

__device__ __forceinline__ void ldsm4(uint32_t* r, uint32_t addr) {
    asm volatile("ldmatrix.sync.aligned.m8n8.x4.shared.b16 {%0,%1,%2,%3}, [%4];"
                 : "=r"(r[0]), "=r"(r[1]), "=r"(r[2]), "=r"(r[3]) : "r"(addr));
}
__device__ __forceinline__ void ldsm4t(uint32_t* r, uint32_t addr) {
    asm volatile("ldmatrix.sync.aligned.m8n8.x4.trans.shared.b16 {%0,%1,%2,%3}, [%4];"
                 : "=r"(r[0]), "=r"(r[1]), "=r"(r[2]), "=r"(r[3]) : "r"(addr));
}

__device__ __forceinline__ void mma16816(float* c, const uint32_t* a, const uint32_t* b) {
    asm volatile("mma.sync.aligned.m16n8k16.row.col.f32.bf16.bf16.f32 "
                 "{%0,%1,%2,%3}, {%4,%5,%6,%7}, {%8,%9}, {%0,%1,%2,%3};"
                 : "+f"(c[0]), "+f"(c[1]), "+f"(c[2]), "+f"(c[3])
                 : "r"(a[0]), "r"(a[1]), "r"(a[2]), "r"(a[3]),
                   "r"(b[0]), "r"(b[1]));
}

#define CP_ASYNC16(s, g) \
    asm volatile("cp.async.cg.shared.global [%0], [%1], 16;" :: "r"(s), "l"(g))
#define CP_COMMIT() asm volatile("cp.async.commit_group;" ::: "memory")
#define CP_WAIT0()  asm volatile("cp.async.wait_group 0;" ::: "memory")

__device__ __forceinline__ uint32_t pack_bf2(float a, float b) {
    __nv_bfloat162 v = __halves2bfloat162(__float2bfloat16(a), __float2bfloat16(b));
    return *(uint32_t*)&v;
}
__device__ __forceinline__ void split1(float v, float& hi_f, float& lo_f) {
    __nv_bfloat16 h = __float2bfloat16(v);
    hi_f = __bfloat162float(h);
    lo_f = v - hi_f;
}

// ---------------------------------------------------------------------------
// Scratch buffers (static __device__ — no allocation allowed)
// ---------------------------------------------------------------------------
#define N_XD   ((size_t)M_ROWS * D_MODEL)
#define N_DD   ((size_t)D_MODEL * D_MODEL)
#define N_DL   ((size_t)D_MODEL * L_LAT)
#define N_ML   ((size_t)M_ROWS * L_LAT)

__device__ __nv_bfloat16 g_xh [N_XD];
__device__ __nv_bfloat16 g_xl [N_XD];
__device__ __nv_bfloat16 g_WqTh[N_DD];
__device__ __nv_bfloat16 g_WqTl[N_DD];
__device__ __nv_bfloat16 g_WkvTh[N_DL];
__device__ __nv_bfloat16 g_WkvTl[N_DL];
__device__ __nv_bfloat16 g_WkTh[N_DL];
__device__ __nv_bfloat16 g_WkTl[N_DL];
__device__ __nv_bfloat16 g_WvTh[N_DL];
__device__ __nv_bfloat16 g_WvTl[N_DL];
__device__ __nv_bfloat16 g_WoTh[N_DD];
__device__ __nv_bfloat16 g_WoTl[N_DD];
__device__ __nv_bfloat16 g_KVh[N_ML];
__device__ __nv_bfloat16 g_KVl[N_ML];
__device__ __nv_bfloat16 g_Qh[N_XD];
__device__ __nv_bfloat16 g_Ql[N_XD];
__device__ __nv_bfloat16 g_Kh[N_XD];
__device__ __nv_bfloat16 g_Kl[N_XD];
__device__ __nv_bfloat16 g_Vh[N_XD];
__device__ __nv_bfloat16 g_Vl[N_XD];
__device__ __nv_bfloat16 g_AOh[N_XD];
__device__ __nv_bfloat16 g_AOl[N_XD];

// ---------------------------------------------------------------------------
// fp32 -> bf16 hi/lo split, row-major (x only)
// ---------------------------------------------------------------------------
__global__ void split_rows(const float4* __restrict__ in,
                           __nv_bfloat162* __restrict__ oh,
                           __nv_bfloat162* __restrict__ ol, int n4)
{
    int i = blockIdx.x * blockDim.x + threadIdx.x;
    if (i >= n4) return;
    float4 v = in[i];
    float h0, l0, h1, l1, h2, l2, h3, l3;
    split1(v.x, h0, l0); split1(v.y, h1, l1);
    split1(v.z, h2, l2); split1(v.w, h3, l3);
    oh[2 * i]     = __halves2bfloat162(__float2bfloat16(h0), __float2bfloat16(h1));
    oh[2 * i + 1] = __halves2bfloat162(__float2bfloat16(h2), __float2bfloat16(h3));
    ol[2 * i]     = __halves2bfloat162(__float2bfloat16(l0), __float2bfloat16(l1));
    ol[2 * i + 1] = __halves2bfloat162(__float2bfloat16(l2), __float2bfloat16(l3));
}

// Transpose + split: in [R,C] fp32 -> out [C,R] bf16 hi/lo
__global__ void split_transpose(const float* __restrict__ in,
                                __nv_bfloat16* __restrict__ oh,
                                __nv_bfloat16* __restrict__ ol, int R, int C)
{
    __shared__ float tile[32][33];
    int c0 = blockIdx.x * 32, r0 = blockIdx.y * 32;
    int tx = threadIdx.x, ty = threadIdx.y;
#pragma unroll
    for (int j = 0; j < 32; j += 8)
        tile[ty + j][tx] = in[(size_t)(r0 + ty + j) * C + c0 + tx];
    __syncthreads();
#pragma unroll
    for (int j = 0; j < 32; j += 8) {
        float v = tile[tx][ty + j];
        __nv_bfloat16 h = __float2bfloat16(v);
        __nv_bfloat16 l = __float2bfloat16(v - __bfloat162float(h));
        size_t o = (size_t)(c0 + ty + j) * R + r0 + tx;
        oh[o] = h;
        ol[o] = l;
    }
}

// ---------------------------------------------------------------------------
// HMMA split-bf16 GEMM: C = A @ B (Bt[N,K] given). Tile 128x128, BK=64,
// 256 threads, SW128-swizzled smem, cp.async double buffer.
// MODE 0: write fp32 C. MODE 1: write split bf16 (Ch, Cl).
// ---------------------------------------------------------------------------
#define GT_BYTES    (128 * 64 * 2)
#define GSTAGE      (4 * GT_BYTES)
#define GSMEM_TOTAL (2 * GSTAGE)

__device__ __forceinline__ void stage_tile(uint32_t sdst,
                                           const __nv_bfloat16* __restrict__ g,
                                           int ldK, int t)
{
#pragma unroll
    for (int j = 0; j < 4; j++) {
        int id = t + 256 * j;
        int r = id >> 3, c = id & 7;
        uint32_t off = (uint32_t)(r * 128 + c * 16);
        off ^= (off >> 3) & 0x70;
        CP_ASYNC16(sdst + off, g + (size_t)r * ldK + c * 8);
    }
}

template <int MODE>
__global__ __launch_bounds__(256, 1)
void gemm_mma(const __nv_bfloat16* __restrict__ Ah, const __nv_bfloat16* __restrict__ Al,
              const __nv_bfloat16* __restrict__ Bh, const __nv_bfloat16* __restrict__ Bl,
              float* __restrict__ C, __nv_bfloat16* __restrict__ Ch,
              __nv_bfloat16* __restrict__ Cl, int Ndim, int Kdim)
{
    extern __shared__ char smc[];
    const uint32_t sb = smem_u32(smc);
    const int t    = threadIdx.x;
    const int lane = t & 31;
    const int w    = t >> 5;
    const int bm   = blockIdx.y * 128;
    const int bn   = blockIdx.x * 128;
    const int m0   = (w >> 2) * 64;
    const int n0   = (w & 3) * 32;

    const __nv_bfloat16* Ahp = Ah + (size_t)bm * Kdim;
    const __nv_bfloat16* Alp = Al + (size_t)bm * Kdim;
    const __nv_bfloat16* Bhp = Bh + (size_t)bn * Kdim;
    const __nv_bfloat16* Blp = Bl + (size_t)bn * Kdim;

    const uint32_t mask = (uint32_t)((lane & 7) << 4);
    const uint32_t akx  = (uint32_t)(((lane >> 4) & 1) * 16);
    const uint32_t bkx  = (uint32_t)(((lane >> 3) & 1) * 16);
    uint32_t arow[4], brow[2];
#pragma unroll
    for (int mt = 0; mt < 4; mt++)
        arow[mt] = (uint32_t)((m0 + 16 * mt + (lane & 7) + ((lane >> 3) & 1) * 8) * 128);
#pragma unroll
    for (int p = 0; p < 2; p++)
        brow[p] = (uint32_t)((n0 + 16 * p + (lane & 7) + ((lane >> 4) & 1) * 8) * 128);

    float acc[4][4][4];
#pragma unroll
    for (int mt = 0; mt < 4; mt++)
#pragma unroll
        for (int nt = 0; nt < 4; nt++)
#pragma unroll
            for (int i = 0; i < 4; i++) acc[mt][nt][i] = 0.0f;

    const int nch = Kdim >> 6;

    stage_tile(sb + 0 * GT_BYTES, Ahp, Kdim, t);
    stage_tile(sb + 1 * GT_BYTES, Alp, Kdim, t);
    stage_tile(sb + 2 * GT_BYTES, Bhp, Kdim, t);
    stage_tile(sb + 3 * GT_BYTES, Blp, Kdim, t);
    CP_COMMIT();

    for (int c = 0; c < nch; ++c) {
        CP_WAIT0();
        __syncthreads();

        if (c + 1 < nch) {
            uint32_t nbase = sb + (uint32_t)(((c + 1) & 1) * GSTAGE);
            size_t ko = (size_t)(c + 1) * 64;
            stage_tile(nbase + 0 * GT_BYTES, Ahp + ko, Kdim, t);
            stage_tile(nbase + 1 * GT_BYTES, Alp + ko, Kdim, t);
            stage_tile(nbase + 2 * GT_BYTES, Bhp + ko, Kdim, t);
            stage_tile(nbase + 3 * GT_BYTES, Blp + ko, Kdim, t);
            CP_COMMIT();
        }

        const uint32_t base = sb + (uint32_t)((c & 1) * GSTAGE);
        const uint32_t sAh = base + 0 * GT_BYTES;
        const uint32_t sAl = base + 1 * GT_BYTES;
        const uint32_t sBh = base + 2 * GT_BYTES;
        const uint32_t sBl = base + 3 * GT_BYTES;

#pragma unroll
        for (int s = 0; s < 4; s++) {
            const uint32_t kb = (uint32_t)(32 * s);
            const uint32_t ka = (kb + akx) ^ mask;
            const uint32_t kB = (kb + bkx) ^ mask;

            uint32_t ah[4][4], al[4][4], bh[4][2], bl[4][2];
#pragma unroll
            for (int mt = 0; mt < 4; mt++) {
                ldsm4(ah[mt], sAh + arow[mt] + ka);
                ldsm4(al[mt], sAl + arow[mt] + ka);
            }
#pragma unroll
            for (int p = 0; p < 2; p++) {
                uint32_t r[4];
                ldsm4(r, sBh + brow[p] + kB);
                bh[2 * p][0] = r[0]; bh[2 * p][1] = r[1];
                bh[2 * p + 1][0] = r[2]; bh[2 * p + 1][1] = r[3];
                ldsm4(r, sBl + brow[p] + kB);
                bl[2 * p][0] = r[0]; bl[2 * p][1] = r[1];
                bl[2 * p + 1][0] = r[2]; bl[2 * p + 1][1] = r[3];
            }
#pragma unroll
            for (int mt = 0; mt < 4; mt++)
#pragma unroll
                for (int nt = 0; nt < 4; nt++) {
                    mma16816(acc[mt][nt], ah[mt], bh[nt]);
                    mma16816(acc[mt][nt], ah[mt], bl[nt]);
                    mma16816(acc[mt][nt], al[mt], bh[nt]);
                }
        }
    }

    const int rbase = bm + m0 + (lane >> 2);
    const int cbase = bn + n0 + (lane & 3) * 2;
#pragma unroll
    for (int mt = 0; mt < 4; mt++)
#pragma unroll
        for (int nt = 0; nt < 4; nt++) {
            const int r0 = rbase + 16 * mt;
            const int cc = cbase + 8 * nt;
            if (MODE == 0) {
                float* p0 = C + (size_t)r0 * Ndim + cc;
                float* p1 = p0 + (size_t)8 * Ndim;
                *(float2*)p0 = make_float2(acc[mt][nt][0], acc[mt][nt][1]);
                *(float2*)p1 = make_float2(acc[mt][nt][2], acc[mt][nt][3]);
            } else {
                float h, l;
                float h0, l0, h1, l1;
                split1(acc[mt][nt][0], h0, l0); split1(acc[mt][nt][1], h1, l1);
                *(uint32_t*)(Ch + (size_t)r0 * Ndim + cc) = pack_bf2(h0, h1);
                *(uint32_t*)(Cl + (size_t)r0 * Ndim + cc) = pack_bf2(l0, l1);
                split1(acc[mt][nt][2], h0, l0); split1(acc[mt][nt][3], h1, l1);
                *(uint32_t*)(Ch + (size_t)(r0 + 8) * Ndim + cc) = pack_bf2(h0, h1);
                *(uint32_t*)(Cl + (size_t)(r0 + 8) * Ndim + cc) = pack_bf2(l0, l1);
                (void)h; (void)l;
            }
        }
}

// ---------------------------------------------------------------------------
// Attention: split-bf16 HMMA flash kernel.
// Block = (64-query tile, head, batch), 128 threads (4 warps, 16 rows each).
// smem: 6 tiles of [2 subtiles][64 rows][64 cols] bf16 (Qh,Ql,Kh,Kl,Vh,Vl).
// ---------------------------------------------------------------------------
#define AT_TILE 16384   // one 64x128 bf16 tile (two 64x64 swizzled subtiles)
#define AT_SMEM (6 * AT_TILE)

__device__ __forceinline__ void stage_qkv(uint32_t dst, const __nv_bfloat16* __restrict__ g,
                                          int t)
{
    // 64 rows x 128 cols bf16, global row stride D_MODEL; two 64-col subtiles
#pragma unroll
    for (int j = 0; j < 8; j++) {
        int id = t + 128 * j;          // 0..1023
        int sub = id >> 9;
        int r = (id >> 3) & 63;
        int u = id & 7;
        uint32_t off = (uint32_t)(r * 128 + u * 16);
        off ^= (off >> 3) & 0x70;
        CP_ASYNC16(dst + sub * 8192 + off, g + (size_t)r * D_MODEL + sub * 64 + u * 8);
    }
}

__global__ __launch_bounds__(128)
void attn_mma(const __nv_bfloat16* __restrict__ Qh, const __nv_bfloat16* __restrict__ Ql,
              const __nv_bfloat16* __restrict__ Kh, const __nv_bfloat16* __restrict__ Kl,
              const __nv_bfloat16* __restrict__ Vh, const __nv_bfloat16* __restrict__ Vl,
              __nv_bfloat16* __restrict__ AOh, __nv_bfloat16* __restrict__ AOl)
{
    extern __shared__ char sma[];
    const uint32_t sb  = smem_u32(sma);
    const uint32_t sQh = sb, sQl = sb + AT_TILE;
    const uint32_t sKh = sb + 2 * AT_TILE, sKl = sb + 3 * AT_TILE;
    const uint32_t sVh = sb + 4 * AT_TILE, sVl = sb + 5 * AT_TILE;

    const int t    = threadIdx.x;
    const int lane = t & 31;
    const int w    = t >> 5;
    const int q0   = blockIdx.x * 64;
    const int h    = blockIdx.y;
    const int b    = blockIdx.z;

    const size_t headoff = (size_t)b * S_LEN * D_MODEL + (size_t)h * HDIM;

    // stage Q (both halves)
    stage_qkv(sQh, Qh + headoff + (size_t)q0 * D_MODEL, t);
    stage_qkv(sQl, Ql + headoff + (size_t)q0 * D_MODEL, t);
    CP_COMMIT();

    // ldmatrix geometry
    const uint32_t mask = (uint32_t)((lane & 7) << 4);
    const uint32_t akx  = (uint32_t)(((lane >> 4) & 1) * 16);
    const uint32_t bkx  = (uint32_t)(((lane >> 3) & 1) * 16);
    const uint32_t arow = (uint32_t)((w * 16 + (lane & 7) + ((lane >> 3) & 1) * 8) * 128);
    uint32_t brow[4];
#pragma unroll
    for (int p = 0; p < 4; p++)
        brow[p] = (uint32_t)((16 * p + (lane & 7) + ((lane >> 4) & 1) * 8) * 128);
    // V trans-ldmatrix lane geometry
    const uint32_t vkey = (uint32_t)(lane & 15);
    const uint32_t vd8  = (lane & 16) ? 16u : 0u;   // byte offset (+8 cols)

    const int qg0 = q0 + w * 16 + (lane >> 2);
    const int qg1 = qg0 + 8;

    float oacc[16][4];
#pragma unroll
    for (int nb = 0; nb < 16; nb++)
#pragma unroll
        for (int i = 0; i < 4; i++) oacc[nb][i] = 0.0f;

    float m0 = -1e30f, m1 = -1e30f, l0 = 0.0f, l1 = 0.0f;
    const float sc2 = 0.12753102833f;   // (1/sqrt(128)) * log2(e)

    for (int c0 = 0; c0 < q0 + 64; c0 += 64) {
        if (!((c0 < PERSIST) || (c0 + 63 >= q0 - (WINDOW - 1)))) continue;

        __syncthreads();   // previous chunk's smem reads done
        stage_qkv(sKh, Kh + headoff + (size_t)c0 * D_MODEL, t);
        stage_qkv(sKl, Kl + headoff + (size_t)c0 * D_MODEL, t);
        stage_qkv(sVh, Vh + headoff + (size_t)c0 * D_MODEL, t);
        stage_qkv(sVl, Vl + headoff + (size_t)c0 * D_MODEL, t);
        CP_COMMIT();
        CP_WAIT0();        // also covers Q stage on first chunk
        __syncthreads();

        // ---- S = Q K^T (3-term split), per warp: 16 rows x 64 keys ----
        float sc[8][4];
#pragma unroll
        for (int nb = 0; nb < 8; nb++)
#pragma unroll
            for (int i = 0; i < 4; i++) sc[nb][i] = 0.0f;

#pragma unroll
        for (int ks = 0; ks < 8; ks++) {
            const uint32_t sub = (uint32_t)((ks >> 2) * 8192);
            const uint32_t kb  = (uint32_t)((ks & 3) * 32);
            const uint32_t ka  = (kb + akx) ^ mask;
            const uint32_t kB  = (kb + bkx) ^ mask;

            uint32_t ah[4], al[4], bh[8][2], bl[8][2];
            ldsm4(ah, sQh + sub + arow + ka);
            ldsm4(al, sQl + sub + arow + ka);
#pragma unroll
            for (int p = 0; p < 4; p++) {
                uint32_t r[4];
                ldsm4(r, sKh + sub + brow[p] + kB);
                bh[2 * p][0] = r[0]; bh[2 * p][1] = r[1];
                bh[2 * p + 1][0] = r[2]; bh[2 * p + 1][1] = r[3];
                ldsm4(r, sKl + sub + brow[p] + kB);
                bl[2 * p][0] = r[0]; bl[2 * p][1] = r[1];
                bl[2 * p + 1][0] = r[2]; bl[2 * p + 1][1] = r[3];
            }
#pragma unroll
            for (int nb = 0; nb < 8; nb++) {
                mma16816(sc[nb], ah, bh[nb]);
                mma16816(sc[nb], ah, bl[nb]);
                mma16816(sc[nb], al, bh[nb]);
            }
        }

        // ---- mask + scale (base-2 domain), row maxes ----
        float mx0 = -1e30f, mx1 = -1e30f;
#pragma unroll
        for (int nb = 0; nb < 8; nb++) {
            const int k0 = c0 + nb * 8 + (lane & 3) * 2;
            const int k1 = k0 + 1;
            bool v00 = (k0 <= qg0) && ((qg0 - k0 < WINDOW) || (k0 < PERSIST));
            bool v01 = (k1 <= qg0) && ((qg0 - k1 < WINDOW) || (k1 < PERSIST));
            bool v10 = (k0 <= qg1) && ((qg1 - k0 < WINDOW) || (k0 < PERSIST));
            bool v11 = (k1 <= qg1) && ((qg1 - k1 < WINDOW) || (k1 < PERSIST));
            sc[nb][0] = v00 ? sc[nb][0] * sc2 : -1e30f;
            sc[nb][1] = v01 ? sc[nb][1] * sc2 : -1e30f;
            sc[nb][2] = v10 ? sc[nb][2] * sc2 : -1e30f;
            sc[nb][3] = v11 ? sc[nb][3] * sc2 : -1e30f;
            mx0 = fmaxf(mx0, fmaxf(sc[nb][0], sc[nb][1]));
            mx1 = fmaxf(mx1, fmaxf(sc[nb][2], sc[nb][3]));
        }
        mx0 = fmaxf(mx0, __shfl_xor_sync(0xffffffffu, mx0, 1));
        mx0 = fmaxf(mx0, __shfl_xor_sync(0xffffffffu, mx0, 2));
        mx1 = fmaxf(mx1, __shfl_xor_sync(0xffffffffu, mx1, 1));
        mx1 = fmaxf(mx1, __shfl_xor_sync(0xffffffffu, mx1, 2));

        const float mn0 = fmaxf(m0, mx0), mn1 = fmaxf(m1, mx1);
        const float f0 = exp2f(m0 - mn0), f1 = exp2f(m1 - mn1);
        m0 = mn0; m1 = mn1;
        l0 *= f0; l1 *= f1;
#pragma unroll
        for (int nb = 0; nb < 16; nb++) {
            oacc[nb][0] *= f0; oacc[nb][1] *= f0;
            oacc[nb][2] *= f1; oacc[nb][3] *= f1;
        }

        // ---- P = exp2(S - m), split into bf16 hi/lo A-fragments ----
        uint32_t pah[4][4], pal[4][4];
        float ps0 = 0.0f, ps1 = 0.0f;
#pragma unroll
        for (int nb = 0; nb < 8; nb++) {
            float p0 = exp2f(sc[nb][0] - mn0);
            float p1 = exp2f(sc[nb][1] - mn0);
            float p2 = exp2f(sc[nb][2] - mn1);
            float p3 = exp2f(sc[nb][3] - mn1);
            ps0 += p0 + p1; ps1 += p2 + p3;
            float h0, e0, h1, e1, h2, e2, h3, e3;
            split1(p0, h0, e0); split1(p1, h1, e1);
            split1(p2, h2, e2); split1(p3, h3, e3);
            const int kb = nb >> 1, half = (nb & 1) * 2;
            pah[kb][half + 0] = pack_bf2(h0, h1);
            pah[kb][half + 1] = pack_bf2(h2, h3);
            pal[kb][half + 0] = pack_bf2(e0, e1);
            pal[kb][half + 1] = pack_bf2(e2, e3);
        }
        ps0 += __shfl_xor_sync(0xffffffffu, ps0, 1);
        ps0 += __shfl_xor_sync(0xffffffffu, ps0, 2);
        ps1 += __shfl_xor_sync(0xffffffffu, ps1, 1);
        ps1 += __shfl_xor_sync(0xffffffffu, ps1, 2);
        l0 += ps0; l1 += ps1;

        // ---- O += P V (3-term split) ----
#pragma unroll
        for (int kb = 0; kb < 4; kb++) {
            const uint32_t keyrow = (uint32_t)((kb * 16 + vkey) * 128);
#pragma unroll
            for (int g = 0; g < 8; g++) {
                const uint32_t sub = (uint32_t)((g >> 2) * 8192);
                uint32_t off = keyrow + (uint32_t)((g & 3) * 32) + vd8;
                off ^= (off >> 3) & 0x70;
                uint32_t rh[4], rl[4];
                ldsm4t(rh, sVh + sub + off);
                ldsm4t(rl, sVl + sub + off);
                uint32_t bvh0[2] = {rh[0], rh[1]}, bvh1[2] = {rh[2], rh[3]};
                uint32_t bvl0[2] = {rl[0], rl[1]}, bvl1[2] = {rl[2], rl[3]};
                mma16816(oacc[2 * g],     pah[kb], bvh0);
                mma16816(oacc[2 * g],     pah[kb], bvl0);
                mma16816(oacc[2 * g],     pal[kb], bvh0);
                mma16816(oacc[2 * g + 1], pah[kb], bvh1);
                mma16816(oacc[2 * g + 1], pah[kb], bvl1);
                mma16816(oacc[2 * g + 1], pal[kb], bvh1);
            }
        }
    }

    // ---- normalize + split-write AO ----
    const float inv0 = 1.0f / l0, inv1 = 1.0f / l1;
    const size_t row0 = (size_t)b * S_LEN + (size_t)qg0;   // qg0 = q0 + w*16 + lane/4
    const size_t row1 = row0 + 8;
#pragma unroll
    for (int nb = 0; nb < 16; nb++) {
        const int d = nb * 8 + (lane & 3) * 2;
        float h0, e0, h1, e1;
        split1(oacc[nb][0] * inv0, h0, e0); split1(oacc[nb][1] * inv0, h1, e1);
        *(uint32_t*)(AOh + row0 * D_MODEL + h * HDIM + d) = pack_bf2(h0, h1);
        *(uint32_t*)(AOl + row0 * D_MODEL + h * HDIM + d) = pack_bf2(e0, e1);
        split1(oacc[nb][2] * inv1, h0, e0); split1(oacc[nb][3] * inv1, h1, e1);
        *(uint32_t*)(AOh + row1 * D_MODEL + h * HDIM + d) = pack_bf2(h0, h1);
        *(uint32_t*)(AOl + row1 * D_MODEL + h * HDIM + d) = pack_bf2(e0, e1);
    }
}

// ---------------------------------------------------------------------------
// Launch
// ---------------------------------------------------------------------------
extern "C" void kernel_launch(void* const* d_in, const int* in_sizes, int n_in,
                              void* d_out, int out_size)
{
    const float* x   = (const float*)d_in[0];
    const float* Wq  = (const float*)d_in[1];
    const float* Wkv = (const float*)d_in[2];
    const float* Wk  = (const float*)d_in[3];
    const float* Wv  = (const float*)d_in[4];
    const float* Wo  = (const float*)d_in[5];
    float* out = (float*)d_out;

    __nv_bfloat16 *xh, *xl, *WqTh, *WqTl, *WkvTh, *WkvTl, *WkTh, *WkTl,
                  *WvTh, *WvTl, *WoTh, *WoTl, *KVh, *KVl,
                  *Qh, *Ql, *Kh, *Kl, *Vh, *Vl, *AOh, *AOl;
    cudaGetSymbolAddress((void**)&xh,    g_xh);
    cudaGetSymbolAddress((void**)&xl,    g_xl);
    cudaGetSymbolAddress((void**)&WqTh,  g_WqTh);
    cudaGetSymbolAddress((void**)&WqTl,  g_WqTl);
    cudaGetSymbolAddress((void**)&WkvTh, g_WkvTh);
    cudaGetSymbolAddress((void**)&WkvTl, g_WkvTl);
    cudaGetSymbolAddress((void**)&WkTh,  g_WkTh);
    cudaGetSymbolAddress((void**)&WkTl,  g_WkTl);
    cudaGetSymbolAddress((void**)&WvTh,  g_WvTh);
    cudaGetSymbolAddress((void**)&WvTl,  g_WvTl);
    cudaGetSymbolAddress((void**)&WoTh,  g_WoTh);
    cudaGetSymbolAddress((void**)&WoTl,  g_WoTl);
    cudaGetSymbolAddress((void**)&KVh,   g_KVh);
    cudaGetSymbolAddress((void**)&KVl,   g_KVl);
    cudaGetSymbolAddress((void**)&Qh,    g_Qh);
    cudaGetSymbolAddress((void**)&Ql,    g_Ql);
    cudaGetSymbolAddress((void**)&Kh,    g_Kh);
    cudaGetSymbolAddress((void**)&Kl,    g_Kl);
    cudaGetSymbolAddress((void**)&Vh,    g_Vh);
    cudaGetSymbolAddress((void**)&Vl,    g_Vl);
    cudaGetSymbolAddress((void**)&AOh,   g_AOh);
    cudaGetSymbolAddress((void**)&AOl,   g_AOl);

    cudaFuncSetAttribute((const void*)gemm_mma<0>,
                         cudaFuncAttributeMaxDynamicSharedMemorySize, GSMEM_TOTAL);
    cudaFuncSetAttribute((const void*)gemm_mma<1>,
                         cudaFuncAttributeMaxDynamicSharedMemorySize, GSMEM_TOTAL);
    cudaFuncSetAttribute((const void*)attn_mma,
                         cudaFuncAttributeMaxDynamicSharedMemorySize, AT_SMEM);

    // launches 1-5 (so launch 6 = Q GEMM gets the ncu capture)
    {
        int n4 = (int)(N_XD / 4);
        split_rows<<<(n4 + 255) / 256, 256>>>((const float4*)x,
                                              (__nv_bfloat162*)xh, (__nv_bfloat162*)xl, n4);
    }
    split_transpose<<<dim3(D_MODEL / 32, D_MODEL / 32), dim3(32, 8)>>>(Wq,  WqTh,  WqTl,  D_MODEL, D_MODEL);
    split_transpose<<<dim3(L_LAT  / 32, D_MODEL / 32), dim3(32, 8)>>>(Wkv, WkvTh, WkvTl, D_MODEL, L_LAT);
    split_transpose<<<dim3(D_MODEL / 32, L_LAT  / 32), dim3(32, 8)>>>(Wk,  WkTh,  WkTl,  L_LAT,  D_MODEL);
    split_transpose<<<dim3(D_MODEL / 32, L_LAT  / 32), dim3(32, 8)>>>(Wv,  WvTh,  WvTl,  L_LAT,  D_MODEL);

    // 6: Q = x @ Wq  (split-bf16 out)
    gemm_mma<1><<<dim3(D_MODEL / 128, M_ROWS / 128), 256, GSMEM_TOTAL>>>(
        xh, xl, WqTh, WqTl, nullptr, Qh, Ql, D_MODEL, D_MODEL);
    // 7: KV = x @ Wkv (split out)
    gemm_mma<1><<<dim3(L_LAT / 128, M_ROWS / 128), 256, GSMEM_TOTAL>>>(
        xh, xl, WkvTh, WkvTl, nullptr, KVh, KVl, L_LAT, D_MODEL);
    // 8,9: K,V = KV @ Wk/Wv (split out)
    gemm_mma<1><<<dim3(D_MODEL / 128, M_ROWS / 128), 256, GSMEM_TOTAL>>>(
        KVh, KVl, WkTh, WkTl, nullptr, Kh, Kl, D_MODEL, L_LAT);
    gemm_mma<1><<<dim3(D_MODEL / 128, M_ROWS / 128), 256, GSMEM_TOTAL>>>(
        KVh, KVl, WvTh, WvTl, nullptr, Vh, Vl, D_MODEL, L_LAT);
    // 10: attention (split-bf16 in, split-bf16 out)
    attn_mma<<<dim3(S_LEN / 64, NHEADS, BATCH), 128, AT_SMEM>>>(
        Qh, Ql, Kh, Kl, Vh, Vl, AOh, AOl);
    // 11: Wo transpose (deferred so GEMM got the profile slot)
    split_transpose<<<dim3(D_MODEL / 32, D_MODEL / 32), dim3(32, 8)>>>(Wo, WoTh, WoTl, D_MODEL, D_MODEL);
    // 12: out = AO @ Wo (fp32 out)
    gemm_mma<0><<<dim3(D_MODEL / 128, M_ROWS / 128), 256, GSMEM_TOTAL>>>(
        AOh, AOl, WoTh, WoTl, out, nullptr, nullptr, D_MODEL, D_MODEL);
}

// round 5
// speedup vs baseline: 3.1172x; 1.0108x over previous
#include <cuda_runtime.h>
#include <cuda_bf16.h>
#include <cstdint>
#include <math.h>

// ---------------------------------------------------------------------------
// Problem constants
// ---------------------------------------------------------------------------
#define S_LEN   2048
#define D_MODEL 2048
#define L_LAT   512
#define BATCH   2
#define NHEADS  16
#define HDIM    128
#define M_ROWS  (BATCH * S_LEN)   // 4096
#define WINDOW  128
#define PERSIST 16

// ---------------------------------------------------------------------------
// PTX helpers
// ---------------------------------------------------------------------------
__device__ __forceinline__ uint32_t smem_u32(const void* p) {
    uint32_t a;
    asm("{ .reg .u64 t; cvta.to.shared.u64 t, %1; cvt.u32.u64 %0, t; }"
        : "=r"(a) : "l"(p));
    return a;
}

__device__ __forceinline__ void ldsm4(uint32_t* r, uint32_t addr) {
    asm volatile("ldmatrix.sync.aligned.m8n8.x4.shared.b16 {%0,%1,%2,%3}, [%4];"
                 : "=r"(r[0]), "=r"(r[1]), "=r"(r[2]), "=r"(r[3]) : "r"(addr));
}
__device__ __forceinline__ void ldsm4t(uint32_t* r, uint32_t addr) {
    asm volatile("ldmatrix.sync.aligned.m8n8.x4.trans.shared.b16 {%0,%1,%2,%3}, [%4];"
                 : "=r"(r[0]), "=r"(r[1]), "=r"(r[2]), "=r"(r[3]) : "r"(addr));
}

__device__ __forceinline__ void mma16816(float* c, const uint32_t* a, const uint32_t* b) {
    asm volatile("mma.sync.aligned.m16n8k16.row.col.f32.bf16.bf16.f32 "
                 "{%0,%1,%2,%3}, {%4,%5,%6,%7}, {%8,%9}, {%0,%1,%2,%3};"
                 : "+f"(c[0]), "+f"(c[1]), "+f"(c[2]), "+f"(c[3])
                 : "r"(a[0]), "r"(a[1]), "r"(a[2]), "r"(a[3]),
                   "r"(b[0]), "r"(b[1]));
}

#define CP_ASYNC16(s, g) \
    asm volatile("cp.async.cg.shared.global [%0], [%1], 16;" :: "r"(s), "l"(g))
#define CP_COMMIT() asm volatile("cp.async.commit_group;" ::: "memory")
#define CP_WAIT0()  asm volatile("cp.async.wait_group 0;" ::: "memory")
#define CP_WAIT1()  asm volatile("cp.async.wait_group 1;" ::: "memory")

__device__ __forceinline__ uint32_t pack_bf2(float a, float b) {
    __nv_bfloat162 v = __halves2bfloat162(__float2bfloat16(a), __float2bfloat16(b));
    return *(uint32_t*)&v;
}
__device__ __forceinline__ void split1(float v, float& hi_f, float& lo_f) {
    __nv_bfloat16 h = __float2bfloat16(v);
    hi_f = __bfloat162float(h);
    lo_f = v - hi_f;
}

// ---------------------------------------------------------------------------
// Scratch buffers
// ---------------------------------------------------------------------------
#define N_XD   ((size_t)M_ROWS * D_MODEL)
#define N_DD   ((size_t)D_MODEL * D_MODEL)
#define N_DL   ((size_t)D_MODEL * L_LAT)
#define N_ML   ((size_t)M_ROWS * L_LAT)

__device__ __nv_bfloat16 g_xh [N_XD];
__device__ __nv_bfloat16 g_xl [N_XD];
__device__ __nv_bfloat16 g_Wqh[N_DD];
__device__ __nv_bfloat16 g_Wql[N_DD];
__device__ __nv_bfloat16 g_Wkvh[N_DL];
__device__ __nv_bfloat16 g_Wkvl[N_DL];
__device__ __nv_bfloat16 g_Wkh[N_DL];
__device__ __nv_bfloat16 g_Wkl[N_DL];
__device__ __nv_bfloat16 g_Wvh[N_DL];
__device__ __nv_bfloat16 g_Wvl[N_DL];
__device__ __nv_bfloat16 g_Woh[N_DD];
__device__ __nv_bfloat16 g_Wol[N_DD];
__device__ __nv_bfloat16 g_KVh[N_ML];
__device__ __nv_bfloat16 g_KVl[N_ML];
__device__ __nv_bfloat16 g_Qh[N_XD];
__device__ __nv_bfloat16 g_Ql[N_XD];
__device__ __nv_bfloat16 g_Kh[N_XD];
__device__ __nv_bfloat16 g_Kl[N_XD];
__device__ __nv_bfloat16 g_Vh[N_XD];
__device__ __nv_bfloat16 g_Vl[N_XD];
__device__ __nv_bfloat16 g_AOh[N_XD];
__device__ __nv_bfloat16 g_AOl[N_XD];

// ---------------------------------------------------------------------------
// fp32 -> bf16 hi/lo split, flat
// ---------------------------------------------------------------------------
__global__ void split_rows(const float4* __restrict__ in,
                           __nv_bfloat162* __restrict__ oh,
                           __nv_bfloat162* __restrict__ ol, int n4)
{
    int i = blockIdx.x * blockDim.x + threadIdx.x;
    if (i >= n4) return;
    float4 v = in[i];
    float h0, l0, h1, l1, h2, l2, h3, l3;
    split1(v.x, h0, l0); split1(v.y, h1, l1);
    split1(v.z, h2, l2); split1(v.w, h3, l3);
    oh[2 * i]     = __halves2bfloat162(__float2bfloat16(h0), __float2bfloat16(h1));
    oh[2 * i + 1] = __halves2bfloat162(__float2bfloat16(h2), __float2bfloat16(h3));
    ol[2 * i]     = __halves2bfloat162(__float2bfloat16(l0), __float2bfloat16(l1));
    ol[2 * i + 1] = __halves2bfloat162(__float2bfloat16(l2), __float2bfloat16(l3));
}

// ---------------------------------------------------------------------------
// HMMA split-bf16 GEMM: C[M,N] = A[M,K] @ B[K,N], B K-major (as stored).
// Tile 128x128, BK=64, 256 threads, 3-stage cp.async pipeline (192 KB smem).
// B operand fragments via ldmatrix.trans (no weight transpose needed).
// MODE 0: fp32 C out. MODE 1: split bf16 (Ch, Cl) out.
// ---------------------------------------------------------------------------
#define GT_BYTES    (128 * 64 * 2)     // 16 KB per operand tile
#define GSTAGE      (4 * GT_BYTES)     // Ah, Al, Bh, Bl = 64 KB
#define GSMEM_TOTAL (3 * GSTAGE)       // 3 stages = 192 KB

// A tile: 128 M-rows x 64 K-cols (128 B rows), SW128 swizzle
__device__ __forceinline__ void stage_a(uint32_t sdst,
                                        const __nv_bfloat16* __restrict__ g,
                                        int ldK, int t)
{
#pragma unroll
    for (int j = 0; j < 4; j++) {
        int id = t + 256 * j;
        int r = id >> 3, c = id & 7;
        uint32_t off = (uint32_t)(r * 128 + c * 16);
        off ^= (off >> 3) & 0x70;
        CP_ASYNC16(sdst + off, g + (size_t)r * ldK + c * 8);
    }
}

// B tile: 64 K-rows x 128 N-cols, two 64-col subtiles of 128 B rows, SW128
__device__ __forceinline__ void stage_b(uint32_t sdst,
                                        const __nv_bfloat16* __restrict__ g,
                                        int ldN, int t)
{
#pragma unroll
    for (int j = 0; j < 4; j++) {
        int id = t + 256 * j;          // 0..1023
        int sub = id >> 9;
        int r = (id >> 3) & 63;
        int u = id & 7;
        uint32_t off = (uint32_t)(r * 128 + u * 16);
        off ^= (off >> 3) & 0x70;
        CP_ASYNC16(sdst + sub * 8192 + off, g + (size_t)r * ldN + sub * 64 + u * 8);
    }
}

template <int MODE>
__global__ __launch_bounds__(256, 1)
void gemm_mma(const __nv_bfloat16* __restrict__ Ah, const __nv_bfloat16* __restrict__ Al,
              const __nv_bfloat16* __restrict__ Bh, const __nv_bfloat16* __restrict__ Bl,
              float* __restrict__ C, __nv_bfloat16* __restrict__ Ch,
              __nv_bfloat16* __restrict__ Cl, int Ndim, int Kdim)
{
    extern __shared__ char smc[];
    const uint32_t sb = smem_u32(smc);
    const int t    = threadIdx.x;
    const int lane = t & 31;
    const int w    = t >> 5;
    const int bm   = blockIdx.y * 128;
    const int bn   = blockIdx.x * 128;
    const int m0   = (w >> 2) * 64;
    const int n0   = (w & 3) * 32;

    const __nv_bfloat16* Ahp = Ah + (size_t)bm * Kdim;
    const __nv_bfloat16* Alp = Al + (size_t)bm * Kdim;
    const __nv_bfloat16* Bhp = Bh + bn;
    const __nv_bfloat16* Blp = Bl + bn;

    // A ldmatrix geometry
    const uint32_t mask = (uint32_t)((lane & 7) << 4);
    const uint32_t akx  = (uint32_t)(((lane >> 4) & 1) * 16);
    uint32_t arow[4];
#pragma unroll
    for (int mt = 0; mt < 4; mt++)
        arow[mt] = (uint32_t)((m0 + 16 * mt + (lane & 7) + ((lane >> 3) & 1) * 8) * 128);
    // B trans-ldmatrix geometry
    const uint32_t vkey  = (uint32_t)(lane & 15);
    const uint32_t vd8   = (lane & 16) ? 16u : 0u;
    const uint32_t nbyte = (uint32_t)((n0 & 63) * 2);
    const uint32_t bsub  = (uint32_t)((n0 >> 6) * 8192);

    float acc[4][4][4];
#pragma unroll
    for (int mt = 0; mt < 4; mt++)
#pragma unroll
        for (int nt = 0; nt < 4; nt++)
#pragma unroll
            for (int i = 0; i < 4; i++) acc[mt][nt][i] = 0.0f;

    const int nch = Kdim >> 6;   // >= 8 for all our shapes

    // prologue: stage chunks 0 and 1
    {
        stage_a(sb + 0 * GT_BYTES, Ahp, Kdim, t);
        stage_a(sb + 1 * GT_BYTES, Alp, Kdim, t);
        stage_b(sb + 2 * GT_BYTES, Bhp, Ndim, t);
        stage_b(sb + 3 * GT_BYTES, Blp, Ndim, t);
        CP_COMMIT();
        uint32_t s1 = sb + GSTAGE;
        stage_a(s1 + 0 * GT_BYTES, Ahp + 64, Kdim, t);
        stage_a(s1 + 1 * GT_BYTES, Alp + 64, Kdim, t);
        stage_b(s1 + 2 * GT_BYTES, Bhp + (size_t)64 * Ndim, Ndim, t);
        stage_b(s1 + 3 * GT_BYTES, Blp + (size_t)64 * Ndim, Ndim, t);
        CP_COMMIT();
    }

    int stg = 0;
    for (int c = 0; c < nch; ++c) {
        if (c + 1 >= nch) { CP_WAIT0(); } else { CP_WAIT1(); }
        __syncthreads();

        if (c + 2 < nch) {
            int ns = stg + 2; if (ns >= 3) ns -= 3;
            uint32_t nb = sb + (uint32_t)(ns * GSTAGE);
            size_t ko = (size_t)(c + 2) * 64;
            stage_a(nb + 0 * GT_BYTES, Ahp + ko, Kdim, t);
            stage_a(nb + 1 * GT_BYTES, Alp + ko, Kdim, t);
            stage_b(nb + 2 * GT_BYTES, Bhp + ko * Ndim, Ndim, t);
            stage_b(nb + 3 * GT_BYTES, Blp + ko * Ndim, Ndim, t);
            CP_COMMIT();
        }

        const uint32_t base = sb + (uint32_t)(stg * GSTAGE);
        const uint32_t sAh = base + 0 * GT_BYTES;
        const uint32_t sAl = base + 1 * GT_BYTES;
        const uint32_t sBh = base + 2 * GT_BYTES;
        const uint32_t sBl = base + 3 * GT_BYTES;

#pragma unroll
        for (int s = 0; s < 4; s++) {
            const uint32_t ka = ((uint32_t)(32 * s) + akx) ^ mask;

            uint32_t ah[4][4], al[4][4], bh[4][2], bl[4][2];
#pragma unroll
            for (int mt = 0; mt < 4; mt++) {
                ldsm4(ah[mt], sAh + arow[mt] + ka);
                ldsm4(al[mt], sAl + arow[mt] + ka);
            }
#pragma unroll
            for (int p = 0; p < 2; p++) {
                uint32_t off = (uint32_t)((s * 16 + vkey) * 128) + nbyte
                             + (uint32_t)(p * 32) + vd8;
                off ^= (off >> 3) & 0x70;
                uint32_t r[4];
                ldsm4t(r, sBh + bsub + off);
                bh[2 * p][0] = r[0]; bh[2 * p][1] = r[1];
                bh[2 * p + 1][0] = r[2]; bh[2 * p + 1][1] = r[3];
                ldsm4t(r, sBl + bsub + off);
                bl[2 * p][0] = r[0]; bl[2 * p][1] = r[1];
                bl[2 * p + 1][0] = r[2]; bl[2 * p + 1][1] = r[3];
            }
#pragma unroll
            for (int mt = 0; mt < 4; mt++)
#pragma unroll
                for (int nt = 0; nt < 4; nt++) {
                    mma16816(acc[mt][nt], ah[mt], bh[nt]);
                    mma16816(acc[mt][nt], ah[mt], bl[nt]);
                    mma16816(acc[mt][nt], al[mt], bh[nt]);
                }
        }
        if (++stg >= 3) stg -= 3;
    }

    const int rbase = bm + m0 + (lane >> 2);
    const int cbase = bn + n0 + (lane & 3) * 2;
#pragma unroll
    for (int mt = 0; mt < 4; mt++)
#pragma unroll
        for (int nt = 0; nt < 4; nt++) {
            const int r0 = rbase + 16 * mt;
            const int cc = cbase + 8 * nt;
            if (MODE == 0) {
                float* p0 = C + (size_t)r0 * Ndim + cc;
                float* p1 = p0 + (size_t)8 * Ndim;
                *(float2*)p0 = make_float2(acc[mt][nt][0], acc[mt][nt][1]);
                *(float2*)p1 = make_float2(acc[mt][nt][2], acc[mt][nt][3]);
            } else {
                float h0, l0, h1, l1;
                split1(acc[mt][nt][0], h0, l0); split1(acc[mt][nt][1], h1, l1);
                *(uint32_t*)(Ch + (size_t)r0 * Ndim + cc) = pack_bf2(h0, h1);
                *(uint32_t*)(Cl + (size_t)r0 * Ndim + cc) = pack_bf2(l0, l1);
                split1(acc[mt][nt][2], h0, l0); split1(acc[mt][nt][3], h1, l1);
                *(uint32_t*)(Ch + (size_t)(r0 + 8) * Ndim + cc) = pack_bf2(h0, h1);
                *(uint32_t*)(Cl + (size_t)(r0 + 8) * Ndim + cc) = pack_bf2(l0, l1);
            }
        }
}

// ---------------------------------------------------------------------------
// Attention: split-bf16 HMMA flash kernel (unchanged from R4)
// ---------------------------------------------------------------------------
#define AT_TILE 16384
#define AT_SMEM (6 * AT_TILE)

__device__ __forceinline__ void stage_qkv(uint32_t dst, const __nv_bfloat16* __restrict__ g,
                                          int t)
{
#pragma unroll
    for (int j = 0; j < 8; j++) {
        int id = t + 128 * j;
        int sub = id >> 9;
        int r = (id >> 3) & 63;
        int u = id & 7;
        uint32_t off = (uint32_t)(r * 128 + u * 16);
        off ^= (off >> 3) & 0x70;
        CP_ASYNC16(dst + sub * 8192 + off, g + (size_t)r * D_MODEL + sub * 64 + u * 8);
    }
}

__global__ __launch_bounds__(128)
void attn_mma(const __nv_bfloat16* __restrict__ Qh, const __nv_bfloat16* __restrict__ Ql,
              const __nv_bfloat16* __restrict__ Kh, const __nv_bfloat16* __restrict__ Kl,
              const __nv_bfloat16* __restrict__ Vh, const __nv_bfloat16* __restrict__ Vl,
              __nv_bfloat16* __restrict__ AOh, __nv_bfloat16* __restrict__ AOl)
{
    extern __shared__ char sma[];
    const uint32_t sb  = smem_u32(sma);
    const uint32_t sQh = sb, sQl = sb + AT_TILE;
    const uint32_t sKh = sb + 2 * AT_TILE, sKl = sb + 3 * AT_TILE;
    const uint32_t sVh = sb + 4 * AT_TILE, sVl = sb + 5 * AT_TILE;

    const int t    = threadIdx.x;
    const int lane = t & 31;
    const int w    = t >> 5;
    const int q0   = blockIdx.x * 64;
    const int h    = blockIdx.y;
    const int b    = blockIdx.z;

    const size_t headoff = (size_t)b * S_LEN * D_MODEL + (size_t)h * HDIM;

    stage_qkv(sQh, Qh + headoff + (size_t)q0 * D_MODEL, t);
    stage_qkv(sQl, Ql + headoff + (size_t)q0 * D_MODEL, t);
    CP_COMMIT();

    const uint32_t mask = (uint32_t)((lane & 7) << 4);
    const uint32_t akx  = (uint32_t)(((lane >> 4) & 1) * 16);
    const uint32_t bkx  = (uint32_t)(((lane >> 3) & 1) * 16);
    const uint32_t arow = (uint32_t)((w * 16 + (lane & 7) + ((lane >> 3) & 1) * 8) * 128);
    uint32_t brow[4];
#pragma unroll
    for (int p = 0; p < 4; p++)
        brow[p] = (uint32_t)((16 * p + (lane & 7) + ((lane >> 4) & 1) * 8) * 128);
    const uint32_t vkey = (uint32_t)(lane & 15);
    const uint32_t vd8  = (lane & 16) ? 16u : 0u;

    const int qg0 = q0 + w * 16 + (lane >> 2);
    const int qg1 = qg0 + 8;

    float oacc[16][4];
#pragma unroll
    for (int nb = 0; nb < 16; nb++)
#pragma unroll
        for (int i = 0; i < 4; i++) oacc[nb][i] = 0.0f;

    float m0 = -1e30f, m1 = -1e30f, l0 = 0.0f, l1 = 0.0f;
    const float sc2 = 0.12753102833f;   // (1/sqrt(128)) * log2(e)

    for (int c0 = 0; c0 < q0 + 64; c0 += 64) {
        if (!((c0 < PERSIST) || (c0 + 63 >= q0 - (WINDOW - 1)))) continue;

        __syncthreads();
        stage_qkv(sKh, Kh + headoff + (size_t)c0 * D_MODEL, t);
        stage_qkv(sKl, Kl + headoff + (size_t)c0 * D_MODEL, t);
        stage_qkv(sVh, Vh + headoff + (size_t)c0 * D_MODEL, t);
        stage_qkv(sVl, Vl + headoff + (size_t)c0 * D_MODEL, t);
        CP_COMMIT();
        CP_WAIT0();
        __syncthreads();

        float sc[8][4];
#pragma unroll
        for (int nb = 0; nb < 8; nb++)
#pragma unroll
            for (int i = 0; i < 4; i++) sc[nb][i] = 0.0f;

#pragma unroll
        for (int ks = 0; ks < 8; ks++) {
            const uint32_t sub = (uint32_t)((ks >> 2) * 8192);
            const uint32_t kb  = (uint32_t)((ks & 3) * 32);
            const uint32_t ka  = (kb + akx) ^ mask;
            const uint32_t kB  = (kb + bkx) ^ mask;

            uint32_t ah[4], al[4], bh[8][2], bl[8][2];
            ldsm4(ah, sQh + sub + arow + ka);
            ldsm4(al, sQl + sub + arow + ka);
#pragma unroll
            for (int p = 0; p < 4; p++) {
                uint32_t r[4];
                ldsm4(r, sKh + sub + brow[p] + kB);
                bh[2 * p][0] = r[0]; bh[2 * p][1] = r[1];
                bh[2 * p + 1][0] = r[2]; bh[2 * p + 1][1] = r[3];
                ldsm4(r, sKl + sub + brow[p] + kB);
                bl[2 * p][0] = r[0]; bl[2 * p][1] = r[1];
                bl[2 * p + 1][0] = r[2]; bl[2 * p + 1][1] = r[3];
            }
#pragma unroll
            for (int nb = 0; nb < 8; nb++) {
                mma16816(sc[nb], ah, bh[nb]);
                mma16816(sc[nb], ah, bl[nb]);
                mma16816(sc[nb], al, bh[nb]);
            }
        }

        float mx0 = -1e30f, mx1 = -1e30f;
#pragma unroll
        for (int nb = 0; nb < 8; nb++) {
            const int k0 = c0 + nb * 8 + (lane & 3) * 2;
            const int k1 = k0 + 1;
            bool v00 = (k0 <= qg0) && ((qg0 - k0 < WINDOW) || (k0 < PERSIST));
            bool v01 = (k1 <= qg0) && ((qg0 - k1 < WINDOW) || (k1 < PERSIST));
            bool v10 = (k0 <= qg1) && ((qg1 - k0 < WINDOW) || (k0 < PERSIST));
            bool v11 = (k1 <= qg1) && ((qg1 - k1 < WINDOW) || (k1 < PERSIST));
            sc[nb][0] = v00 ? sc[nb][0] * sc2 : -1e30f;
            sc[nb][1] = v01 ? sc[nb][1] * sc2 : -1e30f;
            sc[nb][2] = v10 ? sc[nb][2] * sc2 : -1e30f;
            sc[nb][3] = v11 ? sc[nb][3] * sc2 : -1e30f;
            mx0 = fmaxf(mx0, fmaxf(sc[nb][0], sc[nb][1]));
            mx1 = fmaxf(mx1, fmaxf(sc[nb][2], sc[nb][3]));
        }
        mx0 = fmaxf(mx0, __shfl_xor_sync(0xffffffffu, mx0, 1));
        mx0 = fmaxf(mx0, __shfl_xor_sync(0xffffffffu, mx0, 2));
        mx1 = fmaxf(mx1, __shfl_xor_sync(0xffffffffu, mx1, 1));
        mx1 = fmaxf(mx1, __shfl_xor_sync(0xffffffffu, mx1, 2));

        const float mn0 = fmaxf(m0, mx0), mn1 = fmaxf(m1, mx1);
        const float f0 = exp2f(m0 - mn0), f1 = exp2f(m1 - mn1);
        m0 = mn0; m1 = mn1;
        l0 *= f0; l1 *= f1;
#pragma unroll
        for (int nb = 0; nb < 16; nb++) {
            oacc[nb][0] *= f0; oacc[nb][1] *= f0;
            oacc[nb][2] *= f1; oacc[nb][3] *= f1;
        }

        uint32_t pah[4][4], pal[4][4];
        float ps0 = 0.0f, ps1 = 0.0f;
#pragma unroll
        for (int nb = 0; nb < 8; nb++) {
            float p0 = exp2f(sc[nb][0] - mn0);
            float p1 = exp2f(sc[nb][1] - mn0);
            float p2 = exp2f(sc[nb][2] - mn1);
            float p3 = exp2f(sc[nb][3] - mn1);
            ps0 += p0 + p1; ps1 += p2 + p3;
            float h0, e0, h1, e1, h2, e2, h3, e3;
            split1(p0, h0, e0); split1(p1, h1, e1);
            split1(p2, h2, e2); split1(p3, h3, e3);
            const int kb = nb >> 1, half = (nb & 1) * 2;
            pah[kb][half + 0] = pack_bf2(h0, h1);
            pah[kb][half + 1] = pack_bf2(h2, h3);
            pal[kb][half + 0] = pack_bf2(e0, e1);
            pal[kb][half + 1] = pack_bf2(e2, e3);
        }
        ps0 += __shfl_xor_sync(0xffffffffu, ps0, 1);
        ps0 += __shfl_xor_sync(0xffffffffu, ps0, 2);
        ps1 += __shfl_xor_sync(0xffffffffu, ps1, 1);
        ps1 += __shfl_xor_sync(0xffffffffu, ps1, 2);
        l0 += ps0; l1 += ps1;

#pragma unroll
        for (int kb = 0; kb < 4; kb++) {
            const uint32_t keyrow = (uint32_t)((kb * 16 + vkey) * 128);
#pragma unroll
            for (int g = 0; g < 8; g++) {
                const uint32_t sub = (uint32_t)((g >> 2) * 8192);
                uint32_t off = keyrow + (uint32_t)((g & 3) * 32) + vd8;
                off ^= (off >> 3) & 0x70;
                uint32_t rh[4], rl[4];
                ldsm4t(rh, sVh + sub + off);
                ldsm4t(rl, sVl + sub + off);
                uint32_t bvh0[2] = {rh[0], rh[1]}, bvh1[2] = {rh[2], rh[3]};
                uint32_t bvl0[2] = {rl[0], rl[1]}, bvl1[2] = {rl[2], rl[3]};
                mma16816(oacc[2 * g],     pah[kb], bvh0);
                mma16816(oacc[2 * g],     pah[kb], bvl0);
                mma16816(oacc[2 * g],     pal[kb], bvh0);
                mma16816(oacc[2 * g + 1], pah[kb], bvh1);
                mma16816(oacc[2 * g + 1], pah[kb], bvl1);
                mma16816(oacc[2 * g + 1], pal[kb], bvh1);
            }
        }
    }

    const float inv0 = 1.0f / l0, inv1 = 1.0f / l1;
    const size_t row0 = (size_t)b * S_LEN + (size_t)qg0;
    const size_t row1 = row0 + 8;
#pragma unroll
    for (int nb = 0; nb < 16; nb++) {
        const int d = nb * 8 + (lane & 3) * 2;
        float h0, e0, h1, e1;
        split1(oacc[nb][0] * inv0, h0, e0); split1(oacc[nb][1] * inv0, h1, e1);
        *(uint32_t*)(AOh + row0 * D_MODEL + h * HDIM + d) = pack_bf2(h0, h1);
        *(uint32_t*)(AOl + row0 * D_MODEL + h * HDIM + d) = pack_bf2(e0, e1);
        split1(oacc[nb][2] * inv1, h0, e0); split1(oacc[nb][3] * inv1, h1, e1);
        *(uint32_t*)(AOh + row1 * D_MODEL + h * HDIM + d) = pack_bf2(h0, h1);
        *(uint32_t*)(AOl + row1 * D_MODEL + h * HDIM + d) = pack_bf2(e0, e1);
    }
}

// ---------------------------------------------------------------------------
// Launch
// ---------------------------------------------------------------------------
extern "C" void kernel_launch(void* const* d_in, const int* in_sizes, int n_in,
                              void* d_out, int out_size)
{
    const float* x   = (const float*)d_in[0];
    const float* Wq  = (const float*)d_in[1];
    const float* Wkv = (const float*)d_in[2];
    const float* Wk  = (const float*)d_in[3];
    const float* Wv  = (const float*)d_in[4];
    const float* Wo  = (const float*)d_in[5];
    float* out = (float*)d_out;

    __nv_bfloat16 *xh, *xl, *Wqh, *Wql, *Wkvh, *Wkvl, *Wkh, *Wkl,
                  *Wvh, *Wvl, *Woh, *Wol, *KVh, *KVl,
                  *Qh, *Ql, *Kh, *Kl, *Vh, *Vl, *AOh, *AOl;
    cudaGetSymbolAddress((void**)&xh,   g_xh);
    cudaGetSymbolAddress((void**)&xl,   g_xl);
    cudaGetSymbolAddress((void**)&Wqh,  g_Wqh);
    cudaGetSymbolAddress((void**)&Wql,  g_Wql);
    cudaGetSymbolAddress((void**)&Wkvh, g_Wkvh);
    cudaGetSymbolAddress((void**)&Wkvl, g_Wkvl);
    cudaGetSymbolAddress((void**)&Wkh,  g_Wkh);
    cudaGetSymbolAddress((void**)&Wkl,  g_Wkl);
    cudaGetSymbolAddress((void**)&Wvh,  g_Wvh);
    cudaGetSymbolAddress((void**)&Wvl,  g_Wvl);
    cudaGetSymbolAddress((void**)&Woh,  g_Woh);
    cudaGetSymbolAddress((void**)&Wol,  g_Wol);
    cudaGetSymbolAddress((void**)&KVh,  g_KVh);
    cudaGetSymbolAddress((void**)&KVl,  g_KVl);
    cudaGetSymbolAddress((void**)&Qh,   g_Qh);
    cudaGetSymbolAddress((void**)&Ql,   g_Ql);
    cudaGetSymbolAddress((void**)&Kh,   g_Kh);
    cudaGetSymbolAddress((void**)&Kl,   g_Kl);
    cudaGetSymbolAddress((void**)&Vh,   g_Vh);
    cudaGetSymbolAddress((void**)&Vl,   g_Vl);
    cudaGetSymbolAddress((void**)&AOh,  g_AOh);
    cudaGetSymbolAddress((void**)&AOl,  g_AOl);

    cudaFuncSetAttribute((const void*)gemm_mma<0>,
                         cudaFuncAttributeMaxDynamicSharedMemorySize, GSMEM_TOTAL);
    cudaFuncSetAttribute((const void*)gemm_mma<1>,
                         cudaFuncAttributeMaxDynamicSharedMemorySize, GSMEM_TOTAL);
    cudaFuncSetAttribute((const void*)attn_mma,
                         cudaFuncAttributeMaxDynamicSharedMemorySize, AT_SMEM);

    // splits (flat, no transposes)
    split_rows<<<(int)(N_XD / 4 + 255) / 256, 256>>>((const float4*)x,
        (__nv_bfloat162*)xh, (__nv_bfloat162*)xl, (int)(N_XD / 4));
    split_rows<<<(int)(N_DD / 4 + 255) / 256, 256>>>((const float4*)Wq,
        (__nv_bfloat162*)Wqh, (__nv_bfloat162*)Wql, (int)(N_DD / 4));
    split_rows<<<(int)(N_DL / 4 + 255) / 256, 256>>>((const float4*)Wkv,
        (__nv_bfloat162*)Wkvh, (__nv_bfloat162*)Wkvl, (int)(N_DL / 4));
    split_rows<<<(int)(N_DL / 4 + 255) / 256, 256>>>((const float4*)Wk,
        (__nv_bfloat162*)Wkh, (__nv_bfloat162*)Wkl, (int)(N_DL / 4));
    split_rows<<<(int)(N_DL / 4 + 255) / 256, 256>>>((const float4*)Wv,
        (__nv_bfloat162*)Wvh, (__nv_bfloat162*)Wvl, (int)(N_DL / 4));
    split_rows<<<(int)(N_DD / 4 + 255) / 256, 256>>>((const float4*)Wo,
        (__nv_bfloat162*)Woh, (__nv_bfloat162*)Wol, (int)(N_DD / 4));

    // Q = x @ Wq
    gemm_mma<1><<<dim3(D_MODEL / 128, M_ROWS / 128), 256, GSMEM_TOTAL>>>(
        xh, xl, Wqh, Wql, nullptr, Qh, Ql, D_MODEL, D_MODEL);
    // KV = x @ Wkv
    gemm_mma<1><<<dim3(L_LAT / 128, M_ROWS / 128), 256, GSMEM_TOTAL>>>(
        xh, xl, Wkvh, Wkvl, nullptr, KVh, KVl, L_LAT, D_MODEL);
    // K = KV @ Wk ; V = KV @ Wv
    gemm_mma<1><<<dim3(D_MODEL / 128, M_ROWS / 128), 256, GSMEM_TOTAL>>>(
        KVh, KVl, Wkh, Wkl, nullptr, Kh, Kl, D_MODEL, L_LAT);
    gemm_mma<1><<<dim3(D_MODEL / 128, M_ROWS / 128), 256, GSMEM_TOTAL>>>(
        KVh, KVl, Wvh, Wvl, nullptr, Vh, Vl, D_MODEL, L_LAT);
    // attention
    attn_mma<<<dim3(S_LEN / 64, NHEADS, BATCH), 128, AT_SMEM>>>(
        Qh, Ql, Kh, Kl, Vh, Vl, AOh, AOl);
    // out = AO @ Wo
    gemm_mma<0><<<dim3(D_MODEL / 128, M_ROWS / 128), 256, GSMEM_TOTAL>>>(
        AOh, AOl, Woh, Wol, out, nullptr, nullptr, D_MODEL, D_MODEL);
}